// round 12
// baseline (speedup 1.0000x reference)
#include <cuda_runtime.h>
#include <cuda_fp16.h>
#include <math.h>
#include <stdint.h>

#define B_    8
#define T_    12
#define NN_   883
#define DM    152
#define DD2   304
#define SSZ   128
#define NL    3
#define STEPS 288
#define ROWS  (B_*NN_)          /* 7064  */
#define MTOK  (ROWS*T_)         /* 84768 */
#define MTILES ((MTOK+127)/128) /* 663   */

// ---------------- scratch (device globals; no allocs allowed) ----------------
__device__ float  g_s [MTOK];
__device__ float  g_h [MTOK*DM];
__device__ __half g_xn [MTOK*DM];
__device__ __half g_xp [MTOK*DD2];
__device__ __half g_z  [MTOK*DD2];
__device__ __half g_xca[MTOK*DD2];
__device__ __half g_xco[MTOK*DD2];
__device__ __half g_cb [MTOK*DD2];

// transposed fp16 weights: [N rows, K cols]
__device__ __half g_wipdw[NL*2*DD2*DM];   /* 608 x 152 */
__device__ __half g_wcl  [NL*DD2*DD2];
__device__ __half g_w23  [NL*256*DD2];    /* interleaved: row 2j=fc2_j, 2j+1=fc3_j */
__device__ __half g_wf1  [NL*DD2*DD2];
__device__ __half g_wop  [NL*DM*DD2];
__device__ float  g_b23  [NL*256];
__device__ float  g_bipdw[NL*2*DD2];

__device__ __forceinline__ float siluf(float v)     { return v / (1.f + expf(-v)); }
__device__ __forceinline__ float softplusf(float v) { return (v > 20.f) ? v : log1pf(expf(v)); }

__device__ __forceinline__ uint32_t sm2u32(const void* p) {
    uint32_t a;
    asm("{ .reg .u64 t; cvta.to.shared.u64 t, %1; cvt.u32.u64 %0, t; }" : "=r"(a) : "l"(p));
    return a;
}
#define SWZ(o) ((uint32_t)(o) ^ ((((uint32_t)(o)) >> 3) & 0x70u))

__device__ __forceinline__ void ldsm4(uint32_t* r, uint32_t addr) {
    asm volatile("ldmatrix.sync.aligned.m8n8.x4.shared.b16 {%0,%1,%2,%3}, [%4];"
                 : "=r"(r[0]), "=r"(r[1]), "=r"(r[2]), "=r"(r[3]) : "r"(addr));
}
// NOTE: non-volatile — pure register op; lets ptxas sink MMAs into LDSM shadows.
__device__ __forceinline__ void mma16816(float* c, const uint32_t* a, const uint32_t* b) {
    asm("mma.sync.aligned.m16n8k16.row.col.f32.f16.f16.f32 "
        "{%0,%1,%2,%3}, {%4,%5,%6,%7}, {%8,%9}, {%0,%1,%2,%3};"
        : "+f"(c[0]), "+f"(c[1]), "+f"(c[2]), "+f"(c[3])
        : "r"(a[0]), "r"(a[1]), "r"(a[2]), "r"(a[3]), "r"(b[0]), "r"(b[1]));
}
__device__ __forceinline__ void cpa16(uint32_t dst, const void* src, uint32_t sz) {
    asm volatile("cp.async.cg.shared.global [%0], [%1], 16, %2;"
                 :: "r"(dst), "l"(src), "r"(sz) : "memory");
}
__device__ __forceinline__ void cp_commit() {
    asm volatile("cp.async.commit_group;" ::: "memory");
}
template<int N>
__device__ __forceinline__ void cp_wait() {
    asm volatile("cp.async.wait_group %0;" :: "n"(N) : "memory");
}

// ---------------- fused epilogue -------------------------------------------
// EPI: 0 bias->f32 | 3 bias->fp16 | 4 fc1+combine->fp16
//      5 dual fp16: col<DD2 -> xp ; col>=DD2 -> silu -> z
//      6 inline in GEMM (BC pair-product -> atomic s)
template<int EPI>
__device__ __forceinline__ void epi2(int m, int col, int ldc, float v0, float v1,
    const float* __restrict__ bias, float* Cf, __half* Ch, __half* Ch2)
{
    v0 += bias[col]; v1 += bias[col + 1];
    if (EPI == 4) {
        float sv = g_s[m];
        size_t off = (size_t)m * DD2 + col;
        float xc0 = __half2float(g_xco[off]);
        float xc1 = __half2float(g_xco[off + 1]);
        v0 = siluf(xc0 * softplusf(v0) * sv) * __half2float(g_z[off]);
        v1 = siluf(xc1 * softplusf(v1) * sv) * __half2float(g_z[off + 1]);
    }
    if (EPI == 0) {
        *(float2*)(Cf + (size_t)m * ldc + col) = make_float2(v0, v1);
    } else if (EPI == 5) {
        if (col < DD2) {
            *(__half2*)(Ch + (size_t)m * DD2 + col) =
                __halves2half2(__float2half(v0), __float2half(v1));
        } else {
            *(__half2*)(Ch2 + (size_t)m * DD2 + (col - DD2)) =
                __halves2half2(__float2half(siluf(v0)), __float2half(siluf(v1)));
        }
    } else {
        *(__half2*)(Ch + (size_t)m * ldc + col) =
            __halves2half2(__float2half(v0), __float2half(v1));
    }
}

// ---------------- pipelined chunk compute (NKS k-steps) -----------------------
// Addresses: per-thread swizzled base offsets precomputed once; per k-step the
// address is a single XOR with ks*32 (k bits 5-6 are disjoint from the inner
// offset bit 4 and commute through the SW128 swizzle as XOR).
#define STA 0
#define STB 16384
#define STG_SZ 32768
#define SM_TOTAL (2*STG_SZ)

template<int NKS>
__device__ __forceinline__ void gemm_chunk(uint32_t base, const uint32_t* oa,
                                           const uint32_t* ob, float acc[2][8][4])
{
    const uint32_t a0 = base + oa[0], a1 = base + oa[1];
    const uint32_t b0a = base + ob[0], b1a = base + ob[1];
    const uint32_t b2a = base + ob[2], b3a = base + ob[3];
#pragma unroll
    for (int ks = 0; ks < NKS; ks++) {
        const uint32_t kx = (uint32_t)(ks * 32);
        uint32_t ah[2][4];
        ldsm4(ah[0], a0 ^ kx);
        ldsm4(ah[1], a1 ^ kx);
        uint32_t rb[4];
        ldsm4(rb, b0a ^ kx);
#pragma unroll
        for (int p = 0; p < 4; p++) {
            uint32_t rnx[4];
            if (p == 0) ldsm4(rnx, b1a ^ kx);
            if (p == 1) ldsm4(rnx, b2a ^ kx);
            if (p == 2) ldsm4(rnx, b3a ^ kx);
            uint32_t f0[2] = {rb[0], rb[1]}, f1[2] = {rb[2], rb[3]};
            mma16816(acc[0][2*p],   ah[0], f0);
            mma16816(acc[0][2*p+1], ah[0], f1);
            mma16816(acc[1][2*p],   ah[1], f0);
            mma16816(acc[1][2*p+1], ah[1], f1);
            if (p < 3) { rb[0]=rnx[0]; rb[1]=rnx[1]; rb[2]=rnx[2]; rb[3]=rnx[3]; }
        }
    }
}

// ---------------- GEMM: C[M,Nw] = epi(A[M,KV] @ B[Nw,KV]^T + bias) -----------
// CTA tile 128(M) x 128(N), 2-stage cp.async, 2 CTAs/SM.
template<int EPI, int KV>
__global__ void __launch_bounds__(256, 2)
mma_gemm(const __half* __restrict__ A, const __half* __restrict__ B,
         const float* __restrict__ bias,
         float* Cf, __half* Ch, __half* Ch2,
         int M, int Nw, int ldc)
{
    extern __shared__ char smem[];
    const uint32_t sb = sm2u32(smem);
    const int tid  = threadIdx.x;
    const int lane = tid & 31;
    const int wid  = tid >> 5;
    const int wm   = wid & 3;      // 0..3 (M)
    const int wn   = wid >> 2;     // 0..1 (N)
    const int m0   = blockIdx.y * 128;
    const int n0   = blockIdx.x * 128;

    float acc[2][8][4];
#pragma unroll
    for (int i = 0; i < 2; i++)
#pragma unroll
        for (int j = 0; j < 8; j++)
#pragma unroll
            for (int q = 0; q < 4; q++) acc[i][j][q] = 0.f;

    // per-thread swizzled fragment offsets (relative to stage base)
    uint32_t oa[2], ob[4];
    {
#pragma unroll
        for (int mt = 0; mt < 2; mt++) {
            int row = wm * 32 + mt * 16 + (lane & 15);
            oa[mt] = STA + SWZ((uint32_t)(row * 128 + (lane >> 4) * 16));
        }
        const int q    = lane >> 3;
        const int rowo = (q >> 1) * 8 + (lane & 7);
        const int ko   = (q & 1) * 8;
#pragma unroll
        for (int p = 0; p < 4; p++) {
            int row = wn * 64 + p * 16 + rowo;
            ob[p] = STB + SWZ((uint32_t)(row * 128 + ko * 2));
        }
    }

    constexpr int KST  = (KV + 15) >> 4;    // total k16 steps
    constexpr int KC   = (KST + 3) >> 2;    // chunks
    constexpr int TAIL = KST - ((KST >> 2) << 2);  // ksteps in last partial chunk

    auto load_stage = [&](int stg, int k0) {
        uint32_t base = sb + stg * STG_SZ;
#pragma unroll
        for (int i = 0; i < 4; i++) {          // A: 128 rows x 64 k
            int idx = tid + i * 256;
            int r = idx >> 3, u = idx & 7;
            int gm = m0 + r, gk = k0 + u * 8;
            bool ok = (gm < M) && (gk < KV);
            size_t go = (size_t)(ok ? gm : 0) * KV + (ok ? gk : 0);
            cpa16(base + STA + SWZ(r * 128 + u * 16), A + go, ok ? 16u : 0u);
        }
#pragma unroll
        for (int i = 0; i < 4; i++) {          // B: 128 rows x 64 k
            int idx = tid + i * 256;
            int r = idx >> 3, u = idx & 7;
            int gn = n0 + r, gk = k0 + u * 8;
            bool ok = (gn < Nw) && (gk < KV);
            size_t go = (size_t)(ok ? gn : 0) * KV + (ok ? gk : 0);
            cpa16(base + STB + SWZ(r * 128 + u * 16), B + go, ok ? 16u : 0u);
        }
    };

    load_stage(0, 0);
    cp_commit();

    for (int c = 0; c < KC; c++) {
        if (c + 1 < KC) {
            load_stage((c + 1) & 1, (c + 1) << 6);
            cp_commit();
            cp_wait<1>();
        } else {
            cp_wait<0>();
        }
        __syncthreads();

        const uint32_t base = sb + (c & 1) * STG_SZ;
        if (TAIL == 0 || c < KC - 1)
            gemm_chunk<4>(base, oa, ob, acc);
        else
            gemm_chunk<TAIL ? TAIL : 4>(base, oa, ob, acc);
        __syncthreads();
    }

    // ---- epilogue ----
    if (EPI == 6) {
#pragma unroll
        for (int mt = 0; mt < 2; mt++) {
            int r0 = m0 + wm * 32 + mt * 16 + (lane >> 2);
            int r1 = r0 + 8;
            float s0 = 0.f, s1 = 0.f;
#pragma unroll
            for (int nt = 0; nt < 8; nt++) {
                int col = n0 + wn * 64 + nt * 8 + (lane & 3) * 2;
                if (col < Nw) {
                    float b0 = bias[col], b1 = bias[col + 1];
                    s0 += (acc[mt][nt][0] + b0) * (acc[mt][nt][1] + b1);
                    s1 += (acc[mt][nt][2] + b0) * (acc[mt][nt][3] + b1);
                }
            }
            if (r0 < M) atomicAdd(&g_s[r0], s0);
            if (r1 < M) atomicAdd(&g_s[r1], s1);
        }
    } else {
#pragma unroll
        for (int mt = 0; mt < 2; mt++) {
            int r0 = m0 + wm * 32 + mt * 16 + (lane >> 2);
            int r1 = r0 + 8;
#pragma unroll
            for (int nt = 0; nt < 8; nt++) {
                int col = n0 + wn * 64 + nt * 8 + (lane & 3) * 2;
                if (col < Nw) {
                    if (r0 < M) epi2<EPI>(r0, col, ldc, acc[mt][nt][0], acc[mt][nt][1], bias, Cf, Ch, Ch2);
                    if (r1 < M) epi2<EPI>(r1, col, ldc, acc[mt][nt][2], acc[mt][nt][3], bias, Cf, Ch, Ch2);
                }
            }
        }
    }
}

// ---------------- weight prep (ONE launch) -----------------------------------
#define SEG_CL  (DD2*DD2)
#define SEG_23  (256*DD2)
#define SEG_F1  (DD2*DD2)
#define SEG_OP  (DM*DD2)
#define SEG_ALL (SEG_CL+SEG_23+SEG_F1+SEG_OP)
#define R0_END  (NL*2*DD2*DM)
#define R1_END  (R0_END + NL*SEG_ALL)
#define R2_END  (R1_END + NL*2*DD2 + NL*256)

__global__ void wprep_all(const float* __restrict__ inw, const float* __restrict__ dww,
                          const float* __restrict__ cl, const float* __restrict__ f2,
                          const float* __restrict__ f3, const float* __restrict__ f1,
                          const float* __restrict__ op,
                          const float* __restrict__ inb, const float* __restrict__ db,
                          const float* __restrict__ f2b, const float* __restrict__ f3b)
{
    int idx = blockIdx.x * blockDim.x + threadIdx.x;
    if (idx < R0_END) {
        const int PER = 2 * DD2 * DM;
        int l = idx / PER, q = idx % PER;
        int n = q / DM, k = q % DM;
        float v = (n < DD2) ? inw[(size_t)l*DM*DD2 + k*DD2 + n]
                            : dww[(size_t)l*DM*DD2 + k*DD2 + (n - DD2)];
        g_wipdw[idx] = __float2half(v);
    } else if (idx < R1_END) {
        int t = idx - R0_END;
        int l = t / SEG_ALL, r = t % SEG_ALL;
        if (r < SEG_CL) {
            int n = r / DD2, k = r % DD2;
            g_wcl[(long)l*SEG_CL + r] = __float2half(cl[(size_t)l*SEG_CL + (size_t)k*DD2 + n]);
        } else if (r < SEG_CL + SEG_23) {
            int q = r - SEG_CL;
            int n = q / DD2, k = q % DD2;
            int j = n >> 1;
            float v = (n & 1) ? f3[(size_t)l*DD2*SSZ + (size_t)k*SSZ + j]
                              : f2[(size_t)l*DD2*SSZ + (size_t)k*SSZ + j];
            g_w23[(long)l*SEG_23 + q] = __float2half(v);
        } else if (r < SEG_CL + SEG_23 + SEG_F1) {
            int q = r - SEG_CL - SEG_23;
            int n = q / DD2, k = q % DD2;
            g_wf1[(long)l*SEG_F1 + q] = __float2half(f1[(size_t)l*SEG_F1 + (size_t)k*DD2 + n]);
        } else {
            int q = r - SEG_CL - SEG_23 - SEG_F1;
            int n = q / DD2, k = q % DD2;
            g_wop[(long)l*SEG_OP + q] = __float2half(op[(size_t)l*SEG_OP + (size_t)k*DM + n]);
        }
    } else if (idx < R2_END) {
        int t = idx - R1_END;
        const int N1 = NL * 2 * DD2;
        if (t < N1) {
            int l = t / (2*DD2), j = t % (2*DD2);
            g_bipdw[t] = (j < DD2) ? inb[l*DD2 + j] : db[l*DD2 + (j - DD2)];
        } else {
            int q = t - N1;
            int l = q / 256, j = q % 256;
            g_b23[q] = (j & 1) ? f3b[l*SSZ + (j >> 1)] : f2b[l*SSZ + (j >> 1)];
        }
    }
}

// ---------------- embedding (f32 h) ------------------------------------------
__global__ void embed_kernel(const float* __restrict__ x, const float* __restrict__ W_in,
                             const float* __restrict__ b_in, const float* __restrict__ tod,
                             const float* __restrict__ dow, const float* __restrict__ adp)
{
    long idx = blockIdx.x * (long)blockDim.x + threadIdx.x;
    if (idx >= (long)MTOK * DM) return;
    int  c      = (int)(idx % DM);
    long tokidx = idx / DM;
    int  t      = (int)(tokidx % T_);
    long rn     = tokidx / T_;
    int  n      = (int)(rn % NN_);
    int  b      = (int)(rn / NN_);
    const float* xe = x + (((long)(b * T_ + t) * NN_ + n) * 3);
    float v;
    if (c < 24) {
        v = b_in[c] + xe[0]*W_in[c] + xe[1]*W_in[24+c] + xe[2]*W_in[48+c];
    } else if (c < 48) {
        int ti = (int)(xe[1] * (float)STEPS);
        ti = min(max(ti, 0), STEPS - 1);
        v = tod[ti*24 + (c-24)];
    } else if (c < 72) {
        int di = (int)xe[2];
        di = min(max(di, 0), 6);
        v = dow[di*24 + (c-48)];
    } else {
        v = adp[((long)t * NN_ + n) * 80 + (c - 72)];
    }
    g_h[idx] = v;
}

// ---------------- rmsnorm (f32 in, fp16 out) ; zeroes g_s --------------------
__global__ void rmsnorm_kernel(const float* __restrict__ w)
{
    int gwarp = (blockIdx.x * blockDim.x + threadIdx.x) >> 5;
    int lane  = threadIdx.x & 31;
    if (gwarp >= MTOK) return;
    const float* row = g_h + (long)gwarp * DM;
    float ss = 0.f;
    for (int c = lane; c < DM; c += 32) { float v = row[c]; ss += v * v; }
#pragma unroll
    for (int o = 16; o; o >>= 1) ss += __shfl_xor_sync(0xffffffffu, ss, o);
    float scale = rsqrtf(ss / (float)DM + 1e-5f);
    long base = (long)gwarp * DM;
    for (int c = lane; c < DM; c += 32)
        g_xn[base + c] = __float2half(row[c] * scale * w[c]);
    if (!lane) g_s[gwarp] = 0.f;
}

// ---------------- conv over T + silu -> fp16 (warp-aligned shfl) -------------
#define DCHUNKS 10
__global__ void conv_silu_kernel(const float* __restrict__ cw, const float* __restrict__ cb)
{
    __shared__ float w[T_*T_*3];
    __shared__ float bsh[T_];
    for (int i = threadIdx.x; i < T_*T_*3; i += blockDim.x) w[i] = cw[i];
    for (int i = threadIdx.x; i < T_;      i += blockDim.x) bsh[i] = cb[i];
    __syncthreads();

    int gw = (int)((blockIdx.x * (long)blockDim.x + threadIdx.x) >> 5);
    if (gw >= ROWS * DCHUNKS) return;
    int lane = threadIdx.x & 31;
    int r  = gw / DCHUNKS;
    int dc = gw % DCHUNKS;
    int d  = dc * 32 + lane;
    int dl = min(d, DD2 - 1);
    const __half* xrow = g_xp + (long)r * (T_ * DD2);

    float v1[T_];
#pragma unroll
    for (int ti = 0; ti < T_; ti++) v1[ti] = __half2float(xrow[ti*DD2 + dl]);

    float acc[T_];
#pragma unroll
    for (int to = 0; to < T_; to++) acc[to] = bsh[to];

#pragma unroll
    for (int ti = 0; ti < T_; ti++) {
        float v0 = __shfl_up_sync(0xffffffffu, v1[ti], 1);
        float v2 = __shfl_down_sync(0xffffffffu, v1[ti], 1);
        if (lane == 0)  v0 = (d > 0) ? __half2float(xrow[ti*DD2 + d - 1]) : 0.f;
        if (lane == 31) v2 = (d < DD2 - 1) ? __half2float(xrow[ti*DD2 + d + 1]) : 0.f;
        if (d >= DD2 - 1) v2 = 0.f;
#pragma unroll
        for (int to = 0; to < T_; to++) {
            const float* wp = &w[(to*T_ + ti)*3];
            acc[to] += v0*wp[0] + v1[ti]*wp[1] + v2*wp[2];
        }
    }
    if (d < DD2) {
        long obase = (long)r * (T_ * DD2) + d;
#pragma unroll
        for (int to = 0; to < T_; to++)
            g_xca[obase + to*DD2] = __float2half(siluf(acc[to]));
    }
}

// ---------------- head: smem-cached W_out, 16 rows/block, f32 h --------------
#define OUTR 16
__global__ void out_kernel(const float* __restrict__ Wout, const float* __restrict__ bout,
                           float* __restrict__ out)
{
    extern __shared__ float ws[];   // [12][1824] transposed
    for (int i = threadIdx.x; i < T_*DM*12; i += 384) {
        int k = i / 12, j = i % 12;
        ws[j * (T_*DM) + k] = Wout[i];
    }
    __syncthreads();
    int wj   = threadIdx.x >> 5;    // 0..11
    int lane = threadIdx.x & 31;
    const float* wcol = ws + wj * (T_*DM);
    for (int rr = 0; rr < OUTR; rr++) {
        int rn = blockIdx.x * OUTR + rr;
        if (rn >= ROWS) break;
        const float4* row = (const float4*)(g_h + (long)rn * (T_*DM));
        float acc = 0.f;
        for (int k4 = lane; k4 < (T_*DM)/4; k4 += 32) {
            float4 hv = row[k4];
            acc += hv.x * wcol[4*k4] + hv.y * wcol[4*k4+1]
                 + hv.z * wcol[4*k4+2] + hv.w * wcol[4*k4+3];
        }
#pragma unroll
        for (int o = 16; o; o >>= 1) acc += __shfl_xor_sync(0xffffffffu, acc, o);
        if (!lane) {
            int n = rn % NN_, b = rn / NN_;
            out[((long)b * 12 + wj) * NN_ + n] = acc + bout[wj];
        }
    }
}

// =============================================================================
extern "C" void kernel_launch(void* const* d_in, const int* in_sizes, int n_in,
                              void* d_out, int out_size)
{
    (void)in_sizes; (void)n_in; (void)out_size;
    const float* x        = (const float*)d_in[0];
    const float* W_in     = (const float*)d_in[1];
    const float* b_in     = (const float*)d_in[2];
    const float* tod      = (const float*)d_in[3];
    const float* dow      = (const float*)d_in[4];
    const float* adp      = (const float*)d_in[5];
    const float* norm_w   = (const float*)d_in[6];
    const float* inproj_w = (const float*)d_in[7];
    const float* inproj_b = (const float*)d_in[8];
    const float* conv_w   = (const float*)d_in[9];
    const float* conv_b   = (const float*)d_in[10];
    const float* convlin_w= (const float*)d_in[11];
    const float* convlin_b= (const float*)d_in[12];
    const float* fc1_w    = (const float*)d_in[13];
    const float* fc1_b    = (const float*)d_in[14];
    const float* fc2_w    = (const float*)d_in[15];
    const float* fc2_b    = (const float*)d_in[16];
    const float* fc3_w    = (const float*)d_in[17];
    const float* fc3_b    = (const float*)d_in[18];
    /* d_in[19] = A_ssm unused (h0 == 0) */
    const float* D_w      = (const float*)d_in[20];
    const float* D_b      = (const float*)d_in[21];
    const float* outproj_w= (const float*)d_in[22];
    const float* outproj_b= (const float*)d_in[23];
    const float* W_out    = (const float*)d_in[24];
    const float* b_out    = (const float*)d_in[25];
    float* out = (float*)d_out;

    cudaFuncSetAttribute((const void*)mma_gemm<5,152>, cudaFuncAttributeMaxDynamicSharedMemorySize, SM_TOTAL);
    cudaFuncSetAttribute((const void*)mma_gemm<3,304>, cudaFuncAttributeMaxDynamicSharedMemorySize, SM_TOTAL);
    cudaFuncSetAttribute((const void*)mma_gemm<6,304>, cudaFuncAttributeMaxDynamicSharedMemorySize, SM_TOTAL);
    cudaFuncSetAttribute((const void*)mma_gemm<4,304>, cudaFuncAttributeMaxDynamicSharedMemorySize, SM_TOTAL);
    cudaFuncSetAttribute((const void*)mma_gemm<0,304>, cudaFuncAttributeMaxDynamicSharedMemorySize, SM_TOTAL);
    cudaFuncSetAttribute((const void*)out_kernel, cudaFuncAttributeMaxDynamicSharedMemorySize,
                         T_*DM*12*(int)sizeof(float));

    void* p;
#define SYM(sym, var, ty) cudaGetSymbolAddress(&p, sym); ty* var = (ty*)p;
    SYM(g_b23,   b23_p,  float)
    SYM(g_bipdw, bipdw_p,float)
    SYM(g_h,     h_p,    float)
    SYM(g_xn,    xn_p,   __half)
    SYM(g_xp,    xp_p,   __half)
    SYM(g_z,     z_p,    __half)
    SYM(g_xca,   xca_p,  __half)
    SYM(g_xco,   xco_p,  __half)
    SYM(g_cb,    cb_p,   __half)
    SYM(g_wipdw, wpd_p,  __half)
    SYM(g_wcl,   wcl_p,  __half)
    SYM(g_w23,   w23_p,  __half)
    SYM(g_wf1,   wf1_p,  __half)
    SYM(g_wop,   wop_p,  __half)
#undef SYM

    // launch 0: embedding
    {
        long tot = (long)MTOK * DM;
        embed_kernel<<<(int)((tot + 255)/256), 256>>>(x, W_in, b_in, tod, dow, adp);
    }
    // launch 1: rmsnorm layer 0
    rmsnorm_kernel<<<(MTOK*32 + 255)/256, 256>>>(norm_w);
    // launch 2: all weight prep
    wprep_all<<<(R2_END + 255)/256, 256>>>(inproj_w, D_w, convlin_w, fc2_w, fc3_w,
                                           fc1_w, outproj_w, inproj_b, D_b, fc2_b, fc3_b);

    for (int i = 0; i < NL; i++) {
        if (i > 0)
            rmsnorm_kernel<<<(MTOK*32 + 255)/256, 256>>>(norm_w + i*DM);

        // fused inproj|D_w : xn(152) -> xp(fp16) & z(fp16 silu), N=608
        mma_gemm<5,152><<<dim3(5, MTILES), 256, SM_TOTAL>>>(xn_p,
            wpd_p + (long)i*2*DD2*DM, bipdw_p + (long)i*2*DD2,
            nullptr, xp_p, z_p, MTOK, 2*DD2, DD2);

        conv_silu_kernel<<<(ROWS*DCHUNKS*32 + 255)/256, 256>>>(conv_w + i*T_*T_*3, conv_b + i*T_);

        // convlin: xca(304) -> xco fp16(304)
        mma_gemm<3,304><<<dim3(3, MTILES), 256, SM_TOTAL>>>(xca_p,
            wcl_p + (long)i*DD2*DD2, convlin_b + i*DD2,
            nullptr, xco_p, nullptr, MTOK, DD2, DD2);

        // fc2|fc3 interleaved: epilogue computes s via pair products + atomics
        mma_gemm<6,304><<<dim3(2, MTILES), 256, SM_TOTAL>>>(xco_p,
            w23_p + (long)i*256*DD2, b23_p + i*256,
            nullptr, nullptr, nullptr, MTOK, 256, 256);

        // fc1 + combine fused: -> cb fp16(304)
        mma_gemm<4,304><<<dim3(3, MTILES), 256, SM_TOTAL>>>(xco_p,
            wf1_p + (long)i*DD2*DD2, fc1_b + i*DD2,
            nullptr, cb_p, nullptr, MTOK, DD2, DD2);

        // outproj: cb(304) -> h f32(152)
        mma_gemm<0,304><<<dim3(2, MTILES), 256, SM_TOTAL>>>(cb_p,
            wop_p + (long)i*DM*DD2, outproj_b + i*DM,
            h_p, nullptr, nullptr, MTOK, DM, DM);
    }

    out_kernel<<<(ROWS + OUTR - 1)/OUTR, 384, T_*DM*12*sizeof(float)>>>(W_out, b_out, out);
}

// round 13
// speedup vs baseline: 1.0282x; 1.0282x over previous
#include <cuda_runtime.h>
#include <cuda_fp16.h>
#include <math.h>
#include <stdint.h>

#define B_    8
#define T_    12
#define NN_   883
#define DM    152
#define DD2   304
#define SSZ   128
#define NL    3
#define STEPS 288
#define ROWS  (B_*NN_)          /* 7064  */
#define MTOK  (ROWS*T_)         /* 84768 */
#define MTILES ((MTOK+127)/128) /* 663   */

// ---------------- scratch (device globals; no allocs allowed) ----------------
__device__ float  g_s [MTOK];
__device__ float  g_h [MTOK*DM];
__device__ __half g_xn [MTOK*DM];
__device__ __half g_xp [MTOK*DD2];
__device__ __half g_z  [MTOK*DD2];
__device__ __half g_xca[MTOK*DD2];
__device__ __half g_xco[MTOK*DD2];
__device__ __half g_cb [MTOK*DD2];

// transposed fp16 weights: [N rows, K cols]
__device__ __half g_wipdw[NL*2*DD2*DM];   /* 608 x 152 */
__device__ __half g_wcl  [NL*DD2*DD2];
__device__ __half g_w23  [NL*256*DD2];    /* interleaved: row 2j=fc2_j, 2j+1=fc3_j */
__device__ __half g_wf1  [NL*DD2*DD2];
__device__ __half g_wop  [NL*DM*DD2];
__device__ float  g_b23  [NL*256];
__device__ float  g_bipdw[NL*2*DD2];

__device__ __forceinline__ float siluf(float v)     { return v / (1.f + expf(-v)); }
__device__ __forceinline__ float softplusf(float v) { return (v > 20.f) ? v : log1pf(expf(v)); }

__device__ __forceinline__ uint32_t sm2u32(const void* p) {
    uint32_t a;
    asm("{ .reg .u64 t; cvta.to.shared.u64 t, %1; cvt.u32.u64 %0, t; }" : "=r"(a) : "l"(p));
    return a;
}
#define SWZ(o) ((uint32_t)(o) ^ ((((uint32_t)(o)) >> 3) & 0x70u))

__device__ __forceinline__ void ldsm4(uint32_t* r, uint32_t addr) {
    asm volatile("ldmatrix.sync.aligned.m8n8.x4.shared.b16 {%0,%1,%2,%3}, [%4];"
                 : "=r"(r[0]), "=r"(r[1]), "=r"(r[2]), "=r"(r[3]) : "r"(addr));
}
__device__ __forceinline__ void mma16816(float* c, const uint32_t* a, const uint32_t* b) {
    asm("mma.sync.aligned.m16n8k16.row.col.f32.f16.f16.f32 "
        "{%0,%1,%2,%3}, {%4,%5,%6,%7}, {%8,%9}, {%0,%1,%2,%3};"
        : "+f"(c[0]), "+f"(c[1]), "+f"(c[2]), "+f"(c[3])
        : "r"(a[0]), "r"(a[1]), "r"(a[2]), "r"(a[3]), "r"(b[0]), "r"(b[1]));
}
__device__ __forceinline__ void cpa16(uint32_t dst, const void* src, uint32_t sz) {
    asm volatile("cp.async.cg.shared.global [%0], [%1], 16, %2;"
                 :: "r"(dst), "l"(src), "r"(sz) : "memory");
}
__device__ __forceinline__ void cp_commit() {
    asm volatile("cp.async.commit_group;" ::: "memory");
}
template<int N>
__device__ __forceinline__ void cp_wait() {
    asm volatile("cp.async.wait_group %0;" :: "n"(N) : "memory");
}

// ---------------- fused epilogue -------------------------------------------
// EPI: 0 bias->f32 | 3 bias->fp16 | 4 fc1+combine->fp16
//      5 dual fp16: col<DD2 -> xp ; col>=DD2 -> silu -> z
//      6 inline in GEMM (BC pair-product -> atomic s)
template<int EPI>
__device__ __forceinline__ void epi2(int m, int col, int ldc, float v0, float v1,
    const float* __restrict__ bias, float* Cf, __half* Ch, __half* Ch2)
{
    v0 += bias[col]; v1 += bias[col + 1];
    if (EPI == 4) {
        float sv = g_s[m];
        size_t off = (size_t)m * DD2 + col;
        float xc0 = __half2float(g_xco[off]);
        float xc1 = __half2float(g_xco[off + 1]);
        v0 = siluf(xc0 * softplusf(v0) * sv) * __half2float(g_z[off]);
        v1 = siluf(xc1 * softplusf(v1) * sv) * __half2float(g_z[off + 1]);
    }
    if (EPI == 0) {
        *(float2*)(Cf + (size_t)m * ldc + col) = make_float2(v0, v1);
    } else if (EPI == 5) {
        if (col < DD2) {
            *(__half2*)(Ch + (size_t)m * DD2 + col) =
                __halves2half2(__float2half(v0), __float2half(v1));
        } else {
            *(__half2*)(Ch2 + (size_t)m * DD2 + (col - DD2)) =
                __halves2half2(__float2half(siluf(v0)), __float2half(siluf(v1)));
        }
    } else {
        *(__half2*)(Ch + (size_t)m * ldc + col) =
            __halves2half2(__float2half(v0), __float2half(v1));
    }
}

// ---------------- pipelined chunk compute (NKS k-steps, NT n-tiles) ----------
#define STA 0
#define STB 16384
#define STG_SZ 32768
#define SM_TOTAL (2*STG_SZ)

template<int NKS, int NT>
__device__ __forceinline__ void gemm_chunk(uint32_t base, const uint32_t* oa,
                                           const uint32_t* ob, float acc[2][8][4])
{
    if (NT == 0) return;
    constexpr int NP = (NT + 1) / 2;   // B fragments (2 n-tiles each)
    const uint32_t a0 = base + oa[0], a1 = base + oa[1];
#pragma unroll
    for (int ks = 0; ks < NKS; ks++) {
        const uint32_t kx = (uint32_t)(ks * 32);
        uint32_t ah[2][4];
        ldsm4(ah[0], a0 ^ kx);
        ldsm4(ah[1], a1 ^ kx);
        uint32_t rb[4];
        ldsm4(rb, (base + ob[0]) ^ kx);
#pragma unroll
        for (int p = 0; p < NP; p++) {
            uint32_t rnx[4];
            if (p + 1 < NP) ldsm4(rnx, (base + ob[p + 1]) ^ kx);
            uint32_t f0[2] = {rb[0], rb[1]}, f1[2] = {rb[2], rb[3]};
            mma16816(acc[0][2*p],   ah[0], f0);
            mma16816(acc[1][2*p],   ah[1], f0);
            if (2*p + 1 < NT) {
                mma16816(acc[0][2*p+1], ah[0], f1);
                mma16816(acc[1][2*p+1], ah[1], f1);
            }
            if (p + 1 < NP) { rb[0]=rnx[0]; rb[1]=rnx[1]; rb[2]=rnx[2]; rb[3]=rnx[3]; }
        }
    }
}

// ---------------- GEMM: C[M,NWTOT] = epi(A[M,KV] @ B[NWTOT,KV]^T + bias) -----
// CTA tile 128(M) x 128(N), 2-stage cp.async, 2 CTAs/SM.
// NWTOT compile-time: last N-block dispatches to compile-time-trimmed chunks.
template<int EPI, int KV, int NWTOT>
__global__ void __launch_bounds__(256, 2)
mma_gemm(const __half* __restrict__ A, const __half* __restrict__ B,
         const float* __restrict__ bias,
         float* Cf, __half* Ch, __half* Ch2,
         int M, int ldc)
{
    extern __shared__ char smem[];
    const uint32_t sb = sm2u32(smem);
    const int tid  = threadIdx.x;
    const int lane = tid & 31;
    const int wid  = tid >> 5;
    const int wm   = wid & 3;      // 0..3 (M)
    const int wn   = wid >> 2;     // 0..1 (N)
    const int m0   = blockIdx.y * 128;
    const int n0   = blockIdx.x * 128;

    constexpr int NFULL = NWTOT / 128;
    constexpr int NREM  = NWTOT % 128;          // multiple of 8 for all uses
    constexpr int NT0   = NREM ? ((NREM >= 64) ? 8 : NREM / 8) : 8;
    constexpr int NT1   = (NREM > 64) ? (NREM - 64) / 8 : 0;

    const bool full = (NREM == 0) || ((int)blockIdx.x < NFULL);
    const int ntcnt = full ? 8 : (wn ? NT1 : NT0);

    float acc[2][8][4];
#pragma unroll
    for (int i = 0; i < 2; i++)
#pragma unroll
        for (int j = 0; j < 8; j++)
#pragma unroll
            for (int q = 0; q < 4; q++) acc[i][j][q] = 0.f;

    // per-thread swizzled fragment offsets (relative to stage base)
    uint32_t oa[2], ob[4];
    {
#pragma unroll
        for (int mt = 0; mt < 2; mt++) {
            int row = wm * 32 + mt * 16 + (lane & 15);
            oa[mt] = STA + SWZ((uint32_t)(row * 128 + (lane >> 4) * 16));
        }
        const int q    = lane >> 3;
        const int rowo = (q >> 1) * 8 + (lane & 7);
        const int ko   = (q & 1) * 8;
#pragma unroll
        for (int p = 0; p < 4; p++) {
            int row = wn * 64 + p * 16 + rowo;
            ob[p] = STB + SWZ((uint32_t)(row * 128 + ko * 2));
        }
    }

    constexpr int KST  = (KV + 15) >> 4;
    constexpr int KC   = (KST + 3) >> 2;
    constexpr int TAIL = KST - ((KST >> 2) << 2);
    constexpr int TK   = TAIL ? TAIL : 4;

    auto load_stage = [&](int stg, int k0) {
        uint32_t base = sb + stg * STG_SZ;
#pragma unroll
        for (int i = 0; i < 4; i++) {          // A: 128 rows x 64 k
            int idx = tid + i * 256;
            int r = idx >> 3, u = idx & 7;
            int gm = m0 + r, gk = k0 + u * 8;
            bool ok = (gm < M) && (gk < KV);
            size_t go = (size_t)(ok ? gm : 0) * KV + (ok ? gk : 0);
            cpa16(base + STA + SWZ(r * 128 + u * 16), A + go, ok ? 16u : 0u);
        }
#pragma unroll
        for (int i = 0; i < 4; i++) {          // B: 128 rows x 64 k
            int idx = tid + i * 256;
            int r = idx >> 3, u = idx & 7;
            int gn = n0 + r, gk = k0 + u * 8;
            bool ok = (gn < NWTOT) && (gk < KV);
            size_t go = (size_t)(ok ? gn : 0) * KV + (ok ? gk : 0);
            cpa16(base + STB + SWZ(r * 128 + u * 16), B + go, ok ? 16u : 0u);
        }
    };

    load_stage(0, 0);
    cp_commit();

    for (int c = 0; c < KC; c++) {
        if (c + 1 < KC) {
            load_stage((c + 1) & 1, (c + 1) << 6);
            cp_commit();
            cp_wait<1>();
        } else {
            cp_wait<0>();
        }
        __syncthreads();

        const uint32_t base = sb + (c & 1) * STG_SZ;
        const bool lastc = (TAIL != 0) && (c == KC - 1);
        if (full) {
            if (!lastc) gemm_chunk<4, 8>(base, oa, ob, acc);
            else        gemm_chunk<TK, 8>(base, oa, ob, acc);
        } else if (wn == 0) {
            if (!lastc) gemm_chunk<4, NT0>(base, oa, ob, acc);
            else        gemm_chunk<TK, NT0>(base, oa, ob, acc);
        } else {
            if (!lastc) gemm_chunk<4, NT1>(base, oa, ob, acc);
            else        gemm_chunk<TK, NT1>(base, oa, ob, acc);
        }
        __syncthreads();
    }

    // ---- epilogue (column bounds exact by construction; no col guards) ----
    if (EPI == 6) {
#pragma unroll
        for (int mt = 0; mt < 2; mt++) {
            int r0 = m0 + wm * 32 + mt * 16 + (lane >> 2);
            int r1 = r0 + 8;
            float s0 = 0.f, s1 = 0.f;
#pragma unroll
            for (int nt = 0; nt < 8; nt++) {
                int col = n0 + wn * 64 + nt * 8 + (lane & 3) * 2;
                float b0 = bias[col], b1 = bias[col + 1];
                s0 += (acc[mt][nt][0] + b0) * (acc[mt][nt][1] + b1);
                s1 += (acc[mt][nt][2] + b0) * (acc[mt][nt][3] + b1);
            }
            if (r0 < M) atomicAdd(&g_s[r0], s0);
            if (r1 < M) atomicAdd(&g_s[r1], s1);
        }
    } else {
#pragma unroll
        for (int mt = 0; mt < 2; mt++) {
            int r0 = m0 + wm * 32 + mt * 16 + (lane >> 2);
            int r1 = r0 + 8;
#pragma unroll
            for (int nt = 0; nt < 8; nt++) {
                if (nt < ntcnt) {
                    int col = n0 + wn * 64 + nt * 8 + (lane & 3) * 2;
                    if (r0 < M) epi2<EPI>(r0, col, ldc, acc[mt][nt][0], acc[mt][nt][1], bias, Cf, Ch, Ch2);
                    if (r1 < M) epi2<EPI>(r1, col, ldc, acc[mt][nt][2], acc[mt][nt][3], bias, Cf, Ch, Ch2);
                }
            }
        }
    }
}

// ---------------- weight prep (ONE launch) -----------------------------------
#define SEG_CL  (DD2*DD2)
#define SEG_23  (256*DD2)
#define SEG_F1  (DD2*DD2)
#define SEG_OP  (DM*DD2)
#define SEG_ALL (SEG_CL+SEG_23+SEG_F1+SEG_OP)
#define R0_END  (NL*2*DD2*DM)
#define R1_END  (R0_END + NL*SEG_ALL)
#define R2_END  (R1_END + NL*2*DD2 + NL*256)

__global__ void wprep_all(const float* __restrict__ inw, const float* __restrict__ dww,
                          const float* __restrict__ cl, const float* __restrict__ f2,
                          const float* __restrict__ f3, const float* __restrict__ f1,
                          const float* __restrict__ op,
                          const float* __restrict__ inb, const float* __restrict__ db,
                          const float* __restrict__ f2b, const float* __restrict__ f3b)
{
    int idx = blockIdx.x * blockDim.x + threadIdx.x;
    if (idx < R0_END) {
        const int PER = 2 * DD2 * DM;
        int l = idx / PER, q = idx % PER;
        int n = q / DM, k = q % DM;
        float v = (n < DD2) ? inw[(size_t)l*DM*DD2 + k*DD2 + n]
                            : dww[(size_t)l*DM*DD2 + k*DD2 + (n - DD2)];
        g_wipdw[idx] = __float2half(v);
    } else if (idx < R1_END) {
        int t = idx - R0_END;
        int l = t / SEG_ALL, r = t % SEG_ALL;
        if (r < SEG_CL) {
            int n = r / DD2, k = r % DD2;
            g_wcl[(long)l*SEG_CL + r] = __float2half(cl[(size_t)l*SEG_CL + (size_t)k*DD2 + n]);
        } else if (r < SEG_CL + SEG_23) {
            int q = r - SEG_CL;
            int n = q / DD2, k = q % DD2;
            int j = n >> 1;
            float v = (n & 1) ? f3[(size_t)l*DD2*SSZ + (size_t)k*SSZ + j]
                              : f2[(size_t)l*DD2*SSZ + (size_t)k*SSZ + j];
            g_w23[(long)l*SEG_23 + q] = __float2half(v);
        } else if (r < SEG_CL + SEG_23 + SEG_F1) {
            int q = r - SEG_CL - SEG_23;
            int n = q / DD2, k = q % DD2;
            g_wf1[(long)l*SEG_F1 + q] = __float2half(f1[(size_t)l*SEG_F1 + (size_t)k*DD2 + n]);
        } else {
            int q = r - SEG_CL - SEG_23 - SEG_F1;
            int n = q / DD2, k = q % DD2;
            g_wop[(long)l*SEG_OP + q] = __float2half(op[(size_t)l*SEG_OP + (size_t)k*DM + n]);
        }
    } else if (idx < R2_END) {
        int t = idx - R1_END;
        const int N1 = NL * 2 * DD2;
        if (t < N1) {
            int l = t / (2*DD2), j = t % (2*DD2);
            g_bipdw[t] = (j < DD2) ? inb[l*DD2 + j] : db[l*DD2 + (j - DD2)];
        } else {
            int q = t - N1;
            int l = q / 256, j = q % 256;
            g_b23[q] = (j & 1) ? f3b[l*SSZ + (j >> 1)] : f2b[l*SSZ + (j >> 1)];
        }
    }
}

// ---------------- embedding (f32 h) ------------------------------------------
__global__ void embed_kernel(const float* __restrict__ x, const float* __restrict__ W_in,
                             const float* __restrict__ b_in, const float* __restrict__ tod,
                             const float* __restrict__ dow, const float* __restrict__ adp)
{
    long idx = blockIdx.x * (long)blockDim.x + threadIdx.x;
    if (idx >= (long)MTOK * DM) return;
    int  c      = (int)(idx % DM);
    long tokidx = idx / DM;
    int  t      = (int)(tokidx % T_);
    long rn     = tokidx / T_;
    int  n      = (int)(rn % NN_);
    int  b      = (int)(rn / NN_);
    const float* xe = x + (((long)(b * T_ + t) * NN_ + n) * 3);
    float v;
    if (c < 24) {
        v = b_in[c] + xe[0]*W_in[c] + xe[1]*W_in[24+c] + xe[2]*W_in[48+c];
    } else if (c < 48) {
        int ti = (int)(xe[1] * (float)STEPS);
        ti = min(max(ti, 0), STEPS - 1);
        v = tod[ti*24 + (c-24)];
    } else if (c < 72) {
        int di = (int)xe[2];
        di = min(max(di, 0), 6);
        v = dow[di*24 + (c-48)];
    } else {
        v = adp[((long)t * NN_ + n) * 80 + (c - 72)];
    }
    g_h[idx] = v;
}

// ---------------- rmsnorm (f32 in, fp16 out) ; zeroes g_s --------------------
__global__ void rmsnorm_kernel(const float* __restrict__ w)
{
    int gwarp = (blockIdx.x * blockDim.x + threadIdx.x) >> 5;
    int lane  = threadIdx.x & 31;
    if (gwarp >= MTOK) return;
    const float* row = g_h + (long)gwarp * DM;
    float ss = 0.f;
    for (int c = lane; c < DM; c += 32) { float v = row[c]; ss += v * v; }
#pragma unroll
    for (int o = 16; o; o >>= 1) ss += __shfl_xor_sync(0xffffffffu, ss, o);
    float scale = rsqrtf(ss / (float)DM + 1e-5f);
    long base = (long)gwarp * DM;
    for (int c = lane; c < DM; c += 32)
        g_xn[base + c] = __float2half(row[c] * scale * w[c]);
    if (!lane) g_s[gwarp] = 0.f;
}

// ---------------- conv over T + silu -> fp16 (warp-aligned shfl) -------------
#define DCHUNKS 10
__global__ void conv_silu_kernel(const float* __restrict__ cw, const float* __restrict__ cb)
{
    __shared__ float w[T_*T_*3];
    __shared__ float bsh[T_];
    for (int i = threadIdx.x; i < T_*T_*3; i += blockDim.x) w[i] = cw[i];
    for (int i = threadIdx.x; i < T_;      i += blockDim.x) bsh[i] = cb[i];
    __syncthreads();

    int gw = (int)((blockIdx.x * (long)blockDim.x + threadIdx.x) >> 5);
    if (gw >= ROWS * DCHUNKS) return;
    int lane = threadIdx.x & 31;
    int r  = gw / DCHUNKS;
    int dc = gw % DCHUNKS;
    int d  = dc * 32 + lane;
    int dl = min(d, DD2 - 1);
    const __half* xrow = g_xp + (long)r * (T_ * DD2);

    float v1[T_];
#pragma unroll
    for (int ti = 0; ti < T_; ti++) v1[ti] = __half2float(xrow[ti*DD2 + dl]);

    float acc[T_];
#pragma unroll
    for (int to = 0; to < T_; to++) acc[to] = bsh[to];

#pragma unroll
    for (int ti = 0; ti < T_; ti++) {
        float v0 = __shfl_up_sync(0xffffffffu, v1[ti], 1);
        float v2 = __shfl_down_sync(0xffffffffu, v1[ti], 1);
        if (lane == 0)  v0 = (d > 0) ? __half2float(xrow[ti*DD2 + d - 1]) : 0.f;
        if (lane == 31) v2 = (d < DD2 - 1) ? __half2float(xrow[ti*DD2 + d + 1]) : 0.f;
        if (d >= DD2 - 1) v2 = 0.f;
#pragma unroll
        for (int to = 0; to < T_; to++) {
            const float* wp = &w[(to*T_ + ti)*3];
            acc[to] += v0*wp[0] + v1[ti]*wp[1] + v2*wp[2];
        }
    }
    if (d < DD2) {
        long obase = (long)r * (T_ * DD2) + d;
#pragma unroll
        for (int to = 0; to < T_; to++)
            g_xca[obase + to*DD2] = __float2half(siluf(acc[to]));
    }
}

// ---------------- head: smem-cached W_out, 16 rows/block, f32 h --------------
#define OUTR 16
__global__ void out_kernel(const float* __restrict__ Wout, const float* __restrict__ bout,
                           float* __restrict__ out)
{
    extern __shared__ float ws[];   // [12][1824] transposed
    for (int i = threadIdx.x; i < T_*DM*12; i += 384) {
        int k = i / 12, j = i % 12;
        ws[j * (T_*DM) + k] = Wout[i];
    }
    __syncthreads();
    int wj   = threadIdx.x >> 5;    // 0..11
    int lane = threadIdx.x & 31;
    const float* wcol = ws + wj * (T_*DM);
    for (int rr = 0; rr < OUTR; rr++) {
        int rn = blockIdx.x * OUTR + rr;
        if (rn >= ROWS) break;
        const float4* row = (const float4*)(g_h + (long)rn * (T_*DM));
        float acc = 0.f;
        for (int k4 = lane; k4 < (T_*DM)/4; k4 += 32) {
            float4 hv = row[k4];
            acc += hv.x * wcol[4*k4] + hv.y * wcol[4*k4+1]
                 + hv.z * wcol[4*k4+2] + hv.w * wcol[4*k4+3];
        }
#pragma unroll
        for (int o = 16; o; o >>= 1) acc += __shfl_xor_sync(0xffffffffu, acc, o);
        if (!lane) {
            int n = rn % NN_, b = rn / NN_;
            out[((long)b * 12 + wj) * NN_ + n] = acc + bout[wj];
        }
    }
}

// =============================================================================
extern "C" void kernel_launch(void* const* d_in, const int* in_sizes, int n_in,
                              void* d_out, int out_size)
{
    (void)in_sizes; (void)n_in; (void)out_size;
    const float* x        = (const float*)d_in[0];
    const float* W_in     = (const float*)d_in[1];
    const float* b_in     = (const float*)d_in[2];
    const float* tod      = (const float*)d_in[3];
    const float* dow      = (const float*)d_in[4];
    const float* adp      = (const float*)d_in[5];
    const float* norm_w   = (const float*)d_in[6];
    const float* inproj_w = (const float*)d_in[7];
    const float* inproj_b = (const float*)d_in[8];
    const float* conv_w   = (const float*)d_in[9];
    const float* conv_b   = (const float*)d_in[10];
    const float* convlin_w= (const float*)d_in[11];
    const float* convlin_b= (const float*)d_in[12];
    const float* fc1_w    = (const float*)d_in[13];
    const float* fc1_b    = (const float*)d_in[14];
    const float* fc2_w    = (const float*)d_in[15];
    const float* fc2_b    = (const float*)d_in[16];
    const float* fc3_w    = (const float*)d_in[17];
    const float* fc3_b    = (const float*)d_in[18];
    /* d_in[19] = A_ssm unused (h0 == 0) */
    const float* D_w      = (const float*)d_in[20];
    const float* D_b      = (const float*)d_in[21];
    const float* outproj_w= (const float*)d_in[22];
    const float* outproj_b= (const float*)d_in[23];
    const float* W_out    = (const float*)d_in[24];
    const float* b_out    = (const float*)d_in[25];
    float* out = (float*)d_out;

    cudaFuncSetAttribute((const void*)mma_gemm<5,152,608>, cudaFuncAttributeMaxDynamicSharedMemorySize, SM_TOTAL);
    cudaFuncSetAttribute((const void*)mma_gemm<3,304,304>, cudaFuncAttributeMaxDynamicSharedMemorySize, SM_TOTAL);
    cudaFuncSetAttribute((const void*)mma_gemm<6,304,256>, cudaFuncAttributeMaxDynamicSharedMemorySize, SM_TOTAL);
    cudaFuncSetAttribute((const void*)mma_gemm<4,304,304>, cudaFuncAttributeMaxDynamicSharedMemorySize, SM_TOTAL);
    cudaFuncSetAttribute((const void*)mma_gemm<0,304,152>, cudaFuncAttributeMaxDynamicSharedMemorySize, SM_TOTAL);
    cudaFuncSetAttribute((const void*)out_kernel, cudaFuncAttributeMaxDynamicSharedMemorySize,
                         T_*DM*12*(int)sizeof(float));

    void* p;
#define SYM(sym, var, ty) cudaGetSymbolAddress(&p, sym); ty* var = (ty*)p;
    SYM(g_b23,   b23_p,  float)
    SYM(g_bipdw, bipdw_p,float)
    SYM(g_h,     h_p,    float)
    SYM(g_xn,    xn_p,   __half)
    SYM(g_xp,    xp_p,   __half)
    SYM(g_z,     z_p,    __half)
    SYM(g_xca,   xca_p,  __half)
    SYM(g_xco,   xco_p,  __half)
    SYM(g_cb,    cb_p,   __half)
    SYM(g_wipdw, wpd_p,  __half)
    SYM(g_wcl,   wcl_p,  __half)
    SYM(g_w23,   w23_p,  __half)
    SYM(g_wf1,   wf1_p,  __half)
    SYM(g_wop,   wop_p,  __half)
#undef SYM

    // launch 0: embedding
    {
        long tot = (long)MTOK * DM;
        embed_kernel<<<(int)((tot + 255)/256), 256>>>(x, W_in, b_in, tod, dow, adp);
    }
    // launch 1: rmsnorm layer 0
    rmsnorm_kernel<<<(MTOK*32 + 255)/256, 256>>>(norm_w);
    // launch 2: all weight prep
    wprep_all<<<(R2_END + 255)/256, 256>>>(inproj_w, D_w, convlin_w, fc2_w, fc3_w,
                                           fc1_w, outproj_w, inproj_b, D_b, fc2_b, fc3_b);

    for (int i = 0; i < NL; i++) {
        if (i > 0)
            rmsnorm_kernel<<<(MTOK*32 + 255)/256, 256>>>(norm_w + i*DM);

        // fused inproj|D_w : xn(152) -> xp(fp16) & z(fp16 silu), N=608
        mma_gemm<5,152,608><<<dim3(5, MTILES), 256, SM_TOTAL>>>(xn_p,
            wpd_p + (long)i*2*DD2*DM, bipdw_p + (long)i*2*DD2,
            nullptr, xp_p, z_p, MTOK, DD2);

        conv_silu_kernel<<<(ROWS*DCHUNKS*32 + 255)/256, 256>>>(conv_w + i*T_*T_*3, conv_b + i*T_);

        // convlin: xca(304) -> xco fp16(304)
        mma_gemm<3,304,304><<<dim3(3, MTILES), 256, SM_TOTAL>>>(xca_p,
            wcl_p + (long)i*DD2*DD2, convlin_b + i*DD2,
            nullptr, xco_p, nullptr, MTOK, DD2);

        // fc2|fc3 interleaved: epilogue computes s via pair products + atomics
        mma_gemm<6,304,256><<<dim3(2, MTILES), 256, SM_TOTAL>>>(xco_p,
            w23_p + (long)i*256*DD2, b23_p + i*256,
            nullptr, nullptr, nullptr, MTOK, 256);

        // fc1 + combine fused: -> cb fp16(304)
        mma_gemm<4,304,304><<<dim3(3, MTILES), 256, SM_TOTAL>>>(xco_p,
            wf1_p + (long)i*DD2*DD2, fc1_b + i*DD2,
            nullptr, cb_p, nullptr, MTOK, DD2);

        // outproj: cb(304) -> h f32(152)
        mma_gemm<0,304,152><<<dim3(2, MTILES), 256, SM_TOTAL>>>(cb_p,
            wop_p + (long)i*DM*DD2, outproj_b + i*DM,
            h_p, nullptr, nullptr, MTOK, DM);
    }

    out_kernel<<<(ROWS + OUTR - 1)/OUTR, 384, T_*DM*12*sizeof(float)>>>(W_out, b_out, out);
}

// round 14
// speedup vs baseline: 1.1179x; 1.0872x over previous
#include <cuda_runtime.h>
#include <cuda_fp16.h>
#include <math.h>
#include <stdint.h>

#define B_    8
#define T_    12
#define NN_   883
#define DM    152
#define DD2   304
#define SSZ   128
#define NL    3
#define STEPS 288
#define ROWS  (B_*NN_)          /* 7064  */
#define MTOK  (ROWS*T_)         /* 84768 */
#define MTILES ((MTOK+127)/128) /* 663   */

// ---------------- scratch (device globals; no allocs allowed) ----------------
__device__ float  g_s [MTOK];
__device__ float  g_h [MTOK*DM];
__device__ __half g_xn [MTOK*DM];
__device__ __half g_xp [MTOK*DD2];
__device__ __half g_z  [MTOK*DD2];
__device__ __half g_xca[MTOK*DD2];
__device__ __half g_xco[MTOK*DD2];
__device__ __half g_cb [MTOK*DD2];

// transposed fp16 weights: [N rows, K cols]
__device__ __half g_wipdw[NL*2*DD2*DM];   /* 608 x 152 */
__device__ __half g_wcl  [NL*DD2*DD2];
__device__ __half g_w23  [NL*256*DD2];    /* interleaved: row 2j=fc2_j, 2j+1=fc3_j */
__device__ __half g_wf1  [NL*DD2*DD2];
__device__ __half g_wop  [NL*DM*DD2];
__device__ float  g_b23  [NL*256];
__device__ float  g_bipdw[NL*2*DD2];

__device__ __forceinline__ float siluf(float v)     { return v / (1.f + expf(-v)); }
__device__ __forceinline__ float softplusf(float v) { return (v > 20.f) ? v : log1pf(expf(v)); }

__device__ __forceinline__ uint32_t sm2u32(const void* p) {
    uint32_t a;
    asm("{ .reg .u64 t; cvta.to.shared.u64 t, %1; cvt.u32.u64 %0, t; }" : "=r"(a) : "l"(p));
    return a;
}
#define SWZ(o) ((uint32_t)(o) ^ ((((uint32_t)(o)) >> 3) & 0x70u))

__device__ __forceinline__ void ldsm4(uint32_t* r, uint32_t addr) {
    asm volatile("ldmatrix.sync.aligned.m8n8.x4.shared.b16 {%0,%1,%2,%3}, [%4];"
                 : "=r"(r[0]), "=r"(r[1]), "=r"(r[2]), "=r"(r[3]) : "r"(addr));
}
__device__ __forceinline__ void mma16816(float* c, const uint32_t* a, const uint32_t* b) {
    asm("mma.sync.aligned.m16n8k16.row.col.f32.f16.f16.f32 "
        "{%0,%1,%2,%3}, {%4,%5,%6,%7}, {%8,%9}, {%0,%1,%2,%3};"
        : "+f"(c[0]), "+f"(c[1]), "+f"(c[2]), "+f"(c[3])
        : "r"(a[0]), "r"(a[1]), "r"(a[2]), "r"(a[3]), "r"(b[0]), "r"(b[1]));
}
__device__ __forceinline__ void cpa16(uint32_t dst, const void* src, uint32_t sz) {
    asm volatile("cp.async.cg.shared.global [%0], [%1], 16, %2;"
                 :: "r"(dst), "l"(src), "r"(sz) : "memory");
}
__device__ __forceinline__ void cp_commit() {
    asm volatile("cp.async.commit_group;" ::: "memory");
}
template<int N>
__device__ __forceinline__ void cp_wait() {
    asm volatile("cp.async.wait_group %0;" :: "n"(N) : "memory");
}

// ---------------- fused epilogue -------------------------------------------
// EPI: 0 bias->f32 | 3 bias->fp16 | 4 fc1+combine->fp16
//      5 dual fp16: col<DD2 -> xp ; col>=DD2 -> silu -> z
//      6 inline in GEMM (BC pair-product -> atomic s)
template<int EPI>
__device__ __forceinline__ void epi2(int m, int col, int ldc, float v0, float v1,
    const float* __restrict__ bias, float* Cf, __half* Ch, __half* Ch2)
{
    v0 += bias[col]; v1 += bias[col + 1];
    if (EPI == 4) {
        float sv = g_s[m];
        size_t off = (size_t)m * DD2 + col;
        float xc0 = __half2float(g_xco[off]);
        float xc1 = __half2float(g_xco[off + 1]);
        v0 = siluf(xc0 * softplusf(v0) * sv) * __half2float(g_z[off]);
        v1 = siluf(xc1 * softplusf(v1) * sv) * __half2float(g_z[off + 1]);
    }
    if (EPI == 0) {
        *(float2*)(Cf + (size_t)m * ldc + col) = make_float2(v0, v1);
    } else if (EPI == 5) {
        if (col < DD2) {
            *(__half2*)(Ch + (size_t)m * DD2 + col) =
                __halves2half2(__float2half(v0), __float2half(v1));
        } else {
            *(__half2*)(Ch2 + (size_t)m * DD2 + (col - DD2)) =
                __halves2half2(__float2half(siluf(v0)), __float2half(siluf(v1)));
        }
    } else {
        *(__half2*)(Ch + (size_t)m * ldc + col) =
            __halves2half2(__float2half(v0), __float2half(v1));
    }
}

// ---------------- pipelined chunk compute (NKS k-steps, NT<=4 n-tiles) -------
#define STA 0
#define STB 16384
#define STG_SZ 24576
#define SM_TOTAL (2*STG_SZ)

template<int NKS, int NT>
__device__ __forceinline__ void gemm_chunk(uint32_t base, const uint32_t* oa,
                                           const uint32_t* ob, float acc[2][4][4])
{
    if (NT == 0) return;
    constexpr int NP = (NT + 1) / 2;   // B fragments (2 n-tiles each), <=2
    const uint32_t a0 = base + oa[0], a1 = base + oa[1];
#pragma unroll
    for (int ks = 0; ks < NKS; ks++) {
        const uint32_t kx = (uint32_t)(ks * 32);
        uint32_t ah[2][4];
        ldsm4(ah[0], a0 ^ kx);
        ldsm4(ah[1], a1 ^ kx);
        uint32_t rb[4];
        ldsm4(rb, (base + ob[0]) ^ kx);
#pragma unroll
        for (int p = 0; p < NP; p++) {
            uint32_t rnx[4];
            if (p + 1 < NP) ldsm4(rnx, (base + ob[1]) ^ kx);
            uint32_t f0[2] = {rb[0], rb[1]}, f1[2] = {rb[2], rb[3]};
            mma16816(acc[0][2*p],   ah[0], f0);
            mma16816(acc[1][2*p],   ah[1], f0);
            if (2*p + 1 < NT) {
                mma16816(acc[0][2*p+1], ah[0], f1);
                mma16816(acc[1][2*p+1], ah[1], f1);
            }
            if (p + 1 < NP) { rb[0]=rnx[0]; rb[1]=rnx[1]; rb[2]=rnx[2]; rb[3]=rnx[3]; }
        }
    }
}

// ---------------- GEMM: C[M,NWTOT] = epi(A[M,KV] @ B[NWTOT,KV]^T + bias) -----
// CTA tile 128(M) x 64(N), 8 warps = 4M x 2N (warp 32x32), 2-stage cp.async,
// 3 CTAs/SM (48KB smem, <=85 regs). NWTOT compile-time for exact N-trim.
template<int EPI, int KV, int NWTOT>
__global__ void __launch_bounds__(256, 3)
mma_gemm(const __half* __restrict__ A, const __half* __restrict__ B,
         const float* __restrict__ bias,
         float* Cf, __half* Ch, __half* Ch2,
         int M, int ldc)
{
    extern __shared__ char smem[];
    const uint32_t sb = sm2u32(smem);
    const int tid  = threadIdx.x;
    const int lane = tid & 31;
    const int wid  = tid >> 5;
    const int wm   = wid & 3;      // 0..3 (M, 32 rows each)
    const int wn   = wid >> 2;     // 0..1 (N, 32 cols each)
    const int m0   = blockIdx.y * 128;
    const int n0   = blockIdx.x * 64;

    constexpr int NFULL = NWTOT / 64;
    constexpr int NREM  = NWTOT % 64;           // multiple of 8
    constexpr int NT0   = NREM ? ((NREM >= 32) ? 4 : NREM / 8) : 4;
    constexpr int NT1   = (NREM > 32) ? (NREM - 32) / 8 : 0;

    const bool full = (NREM == 0) || ((int)blockIdx.x < NFULL);
    const int ntcnt = full ? 4 : (wn ? NT1 : NT0);

    float acc[2][4][4];
#pragma unroll
    for (int i = 0; i < 2; i++)
#pragma unroll
        for (int j = 0; j < 4; j++)
#pragma unroll
            for (int q = 0; q < 4; q++) acc[i][j][q] = 0.f;

    // per-thread swizzled fragment offsets (relative to stage base)
    uint32_t oa[2], ob[2];
    {
#pragma unroll
        for (int mt = 0; mt < 2; mt++) {
            int row = wm * 32 + mt * 16 + (lane & 15);
            oa[mt] = STA + SWZ((uint32_t)(row * 128 + (lane >> 4) * 16));
        }
        const int q    = lane >> 3;
        const int rowo = (q >> 1) * 8 + (lane & 7);
        const int ko   = (q & 1) * 8;
#pragma unroll
        for (int p = 0; p < 2; p++) {
            int row = wn * 32 + p * 16 + rowo;
            ob[p] = STB + SWZ((uint32_t)(row * 128 + ko * 2));
        }
    }

    constexpr int KST  = (KV + 15) >> 4;
    constexpr int KC   = (KST + 3) >> 2;
    constexpr int TAIL = KST - ((KST >> 2) << 2);
    constexpr int TK   = TAIL ? TAIL : 4;

    auto load_stage = [&](int stg, int k0) {
        uint32_t base = sb + stg * STG_SZ;
#pragma unroll
        for (int i = 0; i < 4; i++) {          // A: 128 rows x 64 k
            int idx = tid + i * 256;
            int r = idx >> 3, u = idx & 7;
            int gm = m0 + r, gk = k0 + u * 8;
            bool ok = (gm < M) && (gk < KV);
            size_t go = (size_t)(ok ? gm : 0) * KV + (ok ? gk : 0);
            cpa16(base + STA + SWZ(r * 128 + u * 16), A + go, ok ? 16u : 0u);
        }
#pragma unroll
        for (int i = 0; i < 2; i++) {          // B: 64 rows x 64 k
            int idx = tid + i * 256;
            int r = idx >> 3, u = idx & 7;
            int gn = n0 + r, gk = k0 + u * 8;
            bool ok = (gn < NWTOT) && (gk < KV);
            size_t go = (size_t)(ok ? gn : 0) * KV + (ok ? gk : 0);
            cpa16(base + STB + SWZ(r * 128 + u * 16), B + go, ok ? 16u : 0u);
        }
    };

    load_stage(0, 0);
    cp_commit();

    for (int c = 0; c < KC; c++) {
        if (c + 1 < KC) {
            load_stage((c + 1) & 1, (c + 1) << 6);
            cp_commit();
            cp_wait<1>();
        } else {
            cp_wait<0>();
        }
        __syncthreads();

        const uint32_t base = sb + (c & 1) * STG_SZ;
        const bool lastc = (TAIL != 0) && (c == KC - 1);
        if (full) {
            if (!lastc) gemm_chunk<4, 4>(base, oa, ob, acc);
            else        gemm_chunk<TK, 4>(base, oa, ob, acc);
        } else if (wn == 0) {
            if (!lastc) gemm_chunk<4, NT0>(base, oa, ob, acc);
            else        gemm_chunk<TK, NT0>(base, oa, ob, acc);
        } else {
            if (!lastc) gemm_chunk<4, NT1>(base, oa, ob, acc);
            else        gemm_chunk<TK, NT1>(base, oa, ob, acc);
        }
        __syncthreads();
    }

    // ---- epilogue (column bounds exact by construction) ----
    if (EPI == 6) {
#pragma unroll
        for (int mt = 0; mt < 2; mt++) {
            int r0 = m0 + wm * 32 + mt * 16 + (lane >> 2);
            int r1 = r0 + 8;
            float s0 = 0.f, s1 = 0.f;
#pragma unroll
            for (int nt = 0; nt < 4; nt++) {
                int col = n0 + wn * 32 + nt * 8 + (lane & 3) * 2;
                float b0 = bias[col], b1 = bias[col + 1];
                s0 += (acc[mt][nt][0] + b0) * (acc[mt][nt][1] + b1);
                s1 += (acc[mt][nt][2] + b0) * (acc[mt][nt][3] + b1);
            }
            if (r0 < M) atomicAdd(&g_s[r0], s0);
            if (r1 < M) atomicAdd(&g_s[r1], s1);
        }
    } else {
#pragma unroll
        for (int mt = 0; mt < 2; mt++) {
            int r0 = m0 + wm * 32 + mt * 16 + (lane >> 2);
            int r1 = r0 + 8;
#pragma unroll
            for (int nt = 0; nt < 4; nt++) {
                if (nt < ntcnt) {
                    int col = n0 + wn * 32 + nt * 8 + (lane & 3) * 2;
                    if (r0 < M) epi2<EPI>(r0, col, ldc, acc[mt][nt][0], acc[mt][nt][1], bias, Cf, Ch, Ch2);
                    if (r1 < M) epi2<EPI>(r1, col, ldc, acc[mt][nt][2], acc[mt][nt][3], bias, Cf, Ch, Ch2);
                }
            }
        }
    }
}

// ---------------- weight prep (ONE launch) -----------------------------------
#define SEG_CL  (DD2*DD2)
#define SEG_23  (256*DD2)
#define SEG_F1  (DD2*DD2)
#define SEG_OP  (DM*DD2)
#define SEG_ALL (SEG_CL+SEG_23+SEG_F1+SEG_OP)
#define R0_END  (NL*2*DD2*DM)
#define R1_END  (R0_END + NL*SEG_ALL)
#define R2_END  (R1_END + NL*2*DD2 + NL*256)

__global__ void wprep_all(const float* __restrict__ inw, const float* __restrict__ dww,
                          const float* __restrict__ cl, const float* __restrict__ f2,
                          const float* __restrict__ f3, const float* __restrict__ f1,
                          const float* __restrict__ op,
                          const float* __restrict__ inb, const float* __restrict__ db,
                          const float* __restrict__ f2b, const float* __restrict__ f3b)
{
    int idx = blockIdx.x * blockDim.x + threadIdx.x;
    if (idx < R0_END) {
        const int PER = 2 * DD2 * DM;
        int l = idx / PER, q = idx % PER;
        int n = q / DM, k = q % DM;
        float v = (n < DD2) ? inw[(size_t)l*DM*DD2 + k*DD2 + n]
                            : dww[(size_t)l*DM*DD2 + k*DD2 + (n - DD2)];
        g_wipdw[idx] = __float2half(v);
    } else if (idx < R1_END) {
        int t = idx - R0_END;
        int l = t / SEG_ALL, r = t % SEG_ALL;
        if (r < SEG_CL) {
            int n = r / DD2, k = r % DD2;
            g_wcl[(long)l*SEG_CL + r] = __float2half(cl[(size_t)l*SEG_CL + (size_t)k*DD2 + n]);
        } else if (r < SEG_CL + SEG_23) {
            int q = r - SEG_CL;
            int n = q / DD2, k = q % DD2;
            int j = n >> 1;
            float v = (n & 1) ? f3[(size_t)l*DD2*SSZ + (size_t)k*SSZ + j]
                              : f2[(size_t)l*DD2*SSZ + (size_t)k*SSZ + j];
            g_w23[(long)l*SEG_23 + q] = __float2half(v);
        } else if (r < SEG_CL + SEG_23 + SEG_F1) {
            int q = r - SEG_CL - SEG_23;
            int n = q / DD2, k = q % DD2;
            g_wf1[(long)l*SEG_F1 + q] = __float2half(f1[(size_t)l*SEG_F1 + (size_t)k*DD2 + n]);
        } else {
            int q = r - SEG_CL - SEG_23 - SEG_F1;
            int n = q / DD2, k = q % DD2;
            g_wop[(long)l*SEG_OP + q] = __float2half(op[(size_t)l*SEG_OP + (size_t)k*DM + n]);
        }
    } else if (idx < R2_END) {
        int t = idx - R1_END;
        const int N1 = NL * 2 * DD2;
        if (t < N1) {
            int l = t / (2*DD2), j = t % (2*DD2);
            g_bipdw[t] = (j < DD2) ? inb[l*DD2 + j] : db[l*DD2 + (j - DD2)];
        } else {
            int q = t - N1;
            int l = q / 256, j = q % 256;
            g_b23[q] = (j & 1) ? f3b[l*SSZ + (j >> 1)] : f2b[l*SSZ + (j >> 1)];
        }
    }
}

// ---------------- embedding (f32 h) ------------------------------------------
__global__ void embed_kernel(const float* __restrict__ x, const float* __restrict__ W_in,
                             const float* __restrict__ b_in, const float* __restrict__ tod,
                             const float* __restrict__ dow, const float* __restrict__ adp)
{
    long idx = blockIdx.x * (long)blockDim.x + threadIdx.x;
    if (idx >= (long)MTOK * DM) return;
    int  c      = (int)(idx % DM);
    long tokidx = idx / DM;
    int  t      = (int)(tokidx % T_);
    long rn     = tokidx / T_;
    int  n      = (int)(rn % NN_);
    int  b      = (int)(rn / NN_);
    const float* xe = x + (((long)(b * T_ + t) * NN_ + n) * 3);
    float v;
    if (c < 24) {
        v = b_in[c] + xe[0]*W_in[c] + xe[1]*W_in[24+c] + xe[2]*W_in[48+c];
    } else if (c < 48) {
        int ti = (int)(xe[1] * (float)STEPS);
        ti = min(max(ti, 0), STEPS - 1);
        v = tod[ti*24 + (c-24)];
    } else if (c < 72) {
        int di = (int)xe[2];
        di = min(max(di, 0), 6);
        v = dow[di*24 + (c-48)];
    } else {
        v = adp[((long)t * NN_ + n) * 80 + (c - 72)];
    }
    g_h[idx] = v;
}

// ---------------- rmsnorm (f32 in, fp16 out) ; zeroes g_s --------------------
__global__ void rmsnorm_kernel(const float* __restrict__ w)
{
    int gwarp = (blockIdx.x * blockDim.x + threadIdx.x) >> 5;
    int lane  = threadIdx.x & 31;
    if (gwarp >= MTOK) return;
    const float* row = g_h + (long)gwarp * DM;
    float ss = 0.f;
    for (int c = lane; c < DM; c += 32) { float v = row[c]; ss += v * v; }
#pragma unroll
    for (int o = 16; o; o >>= 1) ss += __shfl_xor_sync(0xffffffffu, ss, o);
    float scale = rsqrtf(ss / (float)DM + 1e-5f);
    long base = (long)gwarp * DM;
    for (int c = lane; c < DM; c += 32)
        g_xn[base + c] = __float2half(row[c] * scale * w[c]);
    if (!lane) g_s[gwarp] = 0.f;
}

// ---------------- conv over T + silu -> fp16 (warp-aligned shfl) -------------
#define DCHUNKS 10
__global__ void conv_silu_kernel(const float* __restrict__ cw, const float* __restrict__ cb)
{
    __shared__ float w[T_*T_*3];
    __shared__ float bsh[T_];
    for (int i = threadIdx.x; i < T_*T_*3; i += blockDim.x) w[i] = cw[i];
    for (int i = threadIdx.x; i < T_;      i += blockDim.x) bsh[i] = cb[i];
    __syncthreads();

    int gw = (int)((blockIdx.x * (long)blockDim.x + threadIdx.x) >> 5);
    if (gw >= ROWS * DCHUNKS) return;
    int lane = threadIdx.x & 31;
    int r  = gw / DCHUNKS;
    int dc = gw % DCHUNKS;
    int d  = dc * 32 + lane;
    int dl = min(d, DD2 - 1);
    const __half* xrow = g_xp + (long)r * (T_ * DD2);

    float v1[T_];
#pragma unroll
    for (int ti = 0; ti < T_; ti++) v1[ti] = __half2float(xrow[ti*DD2 + dl]);

    float acc[T_];
#pragma unroll
    for (int to = 0; to < T_; to++) acc[to] = bsh[to];

#pragma unroll
    for (int ti = 0; ti < T_; ti++) {
        float v0 = __shfl_up_sync(0xffffffffu, v1[ti], 1);
        float v2 = __shfl_down_sync(0xffffffffu, v1[ti], 1);
        if (lane == 0)  v0 = (d > 0) ? __half2float(xrow[ti*DD2 + d - 1]) : 0.f;
        if (lane == 31) v2 = (d < DD2 - 1) ? __half2float(xrow[ti*DD2 + d + 1]) : 0.f;
        if (d >= DD2 - 1) v2 = 0.f;
#pragma unroll
        for (int to = 0; to < T_; to++) {
            const float* wp = &w[(to*T_ + ti)*3];
            acc[to] += v0*wp[0] + v1[ti]*wp[1] + v2*wp[2];
        }
    }
    if (d < DD2) {
        long obase = (long)r * (T_ * DD2) + d;
#pragma unroll
        for (int to = 0; to < T_; to++)
            g_xca[obase + to*DD2] = __float2half(siluf(acc[to]));
    }
}

// ---------------- head: smem-cached W_out, 16 rows/block, f32 h --------------
#define OUTR 16
__global__ void out_kernel(const float* __restrict__ Wout, const float* __restrict__ bout,
                           float* __restrict__ out)
{
    extern __shared__ float ws[];   // [12][1824] transposed
    for (int i = threadIdx.x; i < T_*DM*12; i += 384) {
        int k = i / 12, j = i % 12;
        ws[j * (T_*DM) + k] = Wout[i];
    }
    __syncthreads();
    int wj   = threadIdx.x >> 5;    // 0..11
    int lane = threadIdx.x & 31;
    const float* wcol = ws + wj * (T_*DM);
    for (int rr = 0; rr < OUTR; rr++) {
        int rn = blockIdx.x * OUTR + rr;
        if (rn >= ROWS) break;
        const float4* row = (const float4*)(g_h + (long)rn * (T_*DM));
        float acc = 0.f;
        for (int k4 = lane; k4 < (T_*DM)/4; k4 += 32) {
            float4 hv = row[k4];
            acc += hv.x * wcol[4*k4] + hv.y * wcol[4*k4+1]
                 + hv.z * wcol[4*k4+2] + hv.w * wcol[4*k4+3];
        }
#pragma unroll
        for (int o = 16; o; o >>= 1) acc += __shfl_xor_sync(0xffffffffu, acc, o);
        if (!lane) {
            int n = rn % NN_, b = rn / NN_;
            out[((long)b * 12 + wj) * NN_ + n] = acc + bout[wj];
        }
    }
}

// =============================================================================
extern "C" void kernel_launch(void* const* d_in, const int* in_sizes, int n_in,
                              void* d_out, int out_size)
{
    (void)in_sizes; (void)n_in; (void)out_size;
    const float* x        = (const float*)d_in[0];
    const float* W_in     = (const float*)d_in[1];
    const float* b_in     = (const float*)d_in[2];
    const float* tod      = (const float*)d_in[3];
    const float* dow      = (const float*)d_in[4];
    const float* adp      = (const float*)d_in[5];
    const float* norm_w   = (const float*)d_in[6];
    const float* inproj_w = (const float*)d_in[7];
    const float* inproj_b = (const float*)d_in[8];
    const float* conv_w   = (const float*)d_in[9];
    const float* conv_b   = (const float*)d_in[10];
    const float* convlin_w= (const float*)d_in[11];
    const float* convlin_b= (const float*)d_in[12];
    const float* fc1_w    = (const float*)d_in[13];
    const float* fc1_b    = (const float*)d_in[14];
    const float* fc2_w    = (const float*)d_in[15];
    const float* fc2_b    = (const float*)d_in[16];
    const float* fc3_w    = (const float*)d_in[17];
    const float* fc3_b    = (const float*)d_in[18];
    /* d_in[19] = A_ssm unused (h0 == 0) */
    const float* D_w      = (const float*)d_in[20];
    const float* D_b      = (const float*)d_in[21];
    const float* outproj_w= (const float*)d_in[22];
    const float* outproj_b= (const float*)d_in[23];
    const float* W_out    = (const float*)d_in[24];
    const float* b_out    = (const float*)d_in[25];
    float* out = (float*)d_out;

    cudaFuncSetAttribute((const void*)mma_gemm<5,152,608>, cudaFuncAttributeMaxDynamicSharedMemorySize, SM_TOTAL);
    cudaFuncSetAttribute((const void*)mma_gemm<3,304,304>, cudaFuncAttributeMaxDynamicSharedMemorySize, SM_TOTAL);
    cudaFuncSetAttribute((const void*)mma_gemm<6,304,256>, cudaFuncAttributeMaxDynamicSharedMemorySize, SM_TOTAL);
    cudaFuncSetAttribute((const void*)mma_gemm<4,304,304>, cudaFuncAttributeMaxDynamicSharedMemorySize, SM_TOTAL);
    cudaFuncSetAttribute((const void*)mma_gemm<0,304,152>, cudaFuncAttributeMaxDynamicSharedMemorySize, SM_TOTAL);
    cudaFuncSetAttribute((const void*)out_kernel, cudaFuncAttributeMaxDynamicSharedMemorySize,
                         T_*DM*12*(int)sizeof(float));

    void* p;
#define SYM(sym, var, ty) cudaGetSymbolAddress(&p, sym); ty* var = (ty*)p;
    SYM(g_b23,   b23_p,  float)
    SYM(g_bipdw, bipdw_p,float)
    SYM(g_h,     h_p,    float)
    SYM(g_xn,    xn_p,   __half)
    SYM(g_xp,    xp_p,   __half)
    SYM(g_z,     z_p,    __half)
    SYM(g_xca,   xca_p,  __half)
    SYM(g_xco,   xco_p,  __half)
    SYM(g_cb,    cb_p,   __half)
    SYM(g_wipdw, wpd_p,  __half)
    SYM(g_wcl,   wcl_p,  __half)
    SYM(g_w23,   w23_p,  __half)
    SYM(g_wf1,   wf1_p,  __half)
    SYM(g_wop,   wop_p,  __half)
#undef SYM

    // launch 0: embedding
    {
        long tot = (long)MTOK * DM;
        embed_kernel<<<(int)((tot + 255)/256), 256>>>(x, W_in, b_in, tod, dow, adp);
    }
    // launch 1: rmsnorm layer 0
    rmsnorm_kernel<<<(MTOK*32 + 255)/256, 256>>>(norm_w);
    // launch 2: all weight prep
    wprep_all<<<(R2_END + 255)/256, 256>>>(inproj_w, D_w, convlin_w, fc2_w, fc3_w,
                                           fc1_w, outproj_w, inproj_b, D_b, fc2_b, fc3_b);

    for (int i = 0; i < NL; i++) {
        if (i > 0)
            rmsnorm_kernel<<<(MTOK*32 + 255)/256, 256>>>(norm_w + i*DM);

        // fused inproj|D_w : xn(152) -> xp(fp16) & z(fp16 silu), N=608
        mma_gemm<5,152,608><<<dim3(10, MTILES), 256, SM_TOTAL>>>(xn_p,
            wpd_p + (long)i*2*DD2*DM, bipdw_p + (long)i*2*DD2,
            nullptr, xp_p, z_p, MTOK, DD2);

        conv_silu_kernel<<<(ROWS*DCHUNKS*32 + 255)/256, 256>>>(conv_w + i*T_*T_*3, conv_b + i*T_);

        // convlin: xca(304) -> xco fp16(304)
        mma_gemm<3,304,304><<<dim3(5, MTILES), 256, SM_TOTAL>>>(xca_p,
            wcl_p + (long)i*DD2*DD2, convlin_b + i*DD2,
            nullptr, xco_p, nullptr, MTOK, DD2);

        // fc2|fc3 interleaved: epilogue computes s via pair products + atomics
        mma_gemm<6,304,256><<<dim3(4, MTILES), 256, SM_TOTAL>>>(xco_p,
            w23_p + (long)i*256*DD2, b23_p + i*256,
            nullptr, nullptr, nullptr, MTOK, 256);

        // fc1 + combine fused: -> cb fp16(304)
        mma_gemm<4,304,304><<<dim3(5, MTILES), 256, SM_TOTAL>>>(xco_p,
            wf1_p + (long)i*DD2*DD2, fc1_b + i*DD2,
            nullptr, cb_p, nullptr, MTOK, DD2);

        // outproj: cb(304) -> h f32(152)
        mma_gemm<0,304,152><<<dim3(3, MTILES), 256, SM_TOTAL>>>(cb_p,
            wop_p + (long)i*DM*DD2, outproj_b + i*DM,
            h_p, nullptr, nullptr, MTOK, DM);
    }

    out_kernel<<<(ROWS + OUTR - 1)/OUTR, 384, T_*DM*12*sizeof(float)>>>(W_out, b_out, out);
}

// round 15
// speedup vs baseline: 1.1506x; 1.0293x over previous
#include <cuda_runtime.h>
#include <cuda_fp16.h>
#include <math.h>
#include <stdint.h>

#define B_    8
#define T_    12
#define NN_   883
#define DM    152
#define DD2   304
#define SSZ   128
#define NL    3
#define STEPS 288
#define ROWS  (B_*NN_)          /* 7064  */
#define MTOK  (ROWS*T_)         /* 84768 */
#define MTILES ((MTOK+127)/128) /* 663   */

// ---------------- scratch (device globals; no allocs allowed) ----------------
__device__ float  g_s [MTOK];
__device__ float  g_h [MTOK*DM];
__device__ __half g_xn [MTOK*DM];
__device__ __half g_xp [MTOK*DD2];
__device__ __half g_z  [MTOK*DD2];
__device__ __half g_xca[MTOK*DD2];
__device__ __half g_xco[MTOK*DD2];
__device__ __half g_cb [MTOK*DD2];

// transposed fp16 weights: [N rows, K cols]
__device__ __half g_wipdw[NL*2*DD2*DM];   /* 608 x 152 */
__device__ __half g_wcl  [NL*DD2*DD2];
__device__ __half g_w23  [NL*256*DD2];    /* interleaved: row 2j=fc2_j, 2j+1=fc3_j */
__device__ __half g_wf1  [NL*DD2*DD2];
__device__ __half g_wop  [NL*DM*DD2];
__device__ float  g_b23  [NL*256];
__device__ float  g_bipdw[NL*2*DD2];

__device__ __forceinline__ float siluf(float v)     { return v / (1.f + expf(-v)); }
__device__ __forceinline__ float softplusf(float v) { return (v > 20.f) ? v : log1pf(expf(v)); }

__device__ __forceinline__ uint32_t sm2u32(const void* p) {
    uint32_t a;
    asm("{ .reg .u64 t; cvta.to.shared.u64 t, %1; cvt.u32.u64 %0, t; }" : "=r"(a) : "l"(p));
    return a;
}
#define SWZ(o) ((uint32_t)(o) ^ ((((uint32_t)(o)) >> 3) & 0x70u))

__device__ __forceinline__ void ldsm4(uint32_t* r, uint32_t addr) {
    asm volatile("ldmatrix.sync.aligned.m8n8.x4.shared.b16 {%0,%1,%2,%3}, [%4];"
                 : "=r"(r[0]), "=r"(r[1]), "=r"(r[2]), "=r"(r[3]) : "r"(addr));
}
__device__ __forceinline__ void mma16816(float* c, const uint32_t* a, const uint32_t* b) {
    asm("mma.sync.aligned.m16n8k16.row.col.f32.f16.f16.f32 "
        "{%0,%1,%2,%3}, {%4,%5,%6,%7}, {%8,%9}, {%0,%1,%2,%3};"
        : "+f"(c[0]), "+f"(c[1]), "+f"(c[2]), "+f"(c[3])
        : "r"(a[0]), "r"(a[1]), "r"(a[2]), "r"(a[3]), "r"(b[0]), "r"(b[1]));
}
__device__ __forceinline__ void cpa16(uint32_t dst, const void* src, uint32_t sz) {
    asm volatile("cp.async.cg.shared.global [%0], [%1], 16, %2;"
                 :: "r"(dst), "l"(src), "r"(sz) : "memory");
}
__device__ __forceinline__ void cp_commit() {
    asm volatile("cp.async.commit_group;" ::: "memory");
}
template<int N>
__device__ __forceinline__ void cp_wait() {
    asm volatile("cp.async.wait_group %0;" :: "n"(N) : "memory");
}

// ---------------- fused epilogue -------------------------------------------
// EPI: 0 bias->f32 | 3 bias->fp16 | 4 fc1+combine->fp16
//      5 dual fp16: col<DD2 -> xp ; col>=DD2 -> silu -> z
//      6 inline in GEMM (BC pair-product -> atomic s)
template<int EPI>
__device__ __forceinline__ void epi2(int m, int col, int ldc, float v0, float v1,
    const float* __restrict__ bias, float* Cf, __half* Ch, __half* Ch2)
{
    v0 += bias[col]; v1 += bias[col + 1];
    if (EPI == 4) {
        float sv = g_s[m];
        size_t off = (size_t)m * DD2 + col;
        float xc0 = __half2float(g_xco[off]);
        float xc1 = __half2float(g_xco[off + 1]);
        v0 = siluf(xc0 * softplusf(v0) * sv) * __half2float(g_z[off]);
        v1 = siluf(xc1 * softplusf(v1) * sv) * __half2float(g_z[off + 1]);
    }
    if (EPI == 0) {
        *(float2*)(Cf + (size_t)m * ldc + col) = make_float2(v0, v1);
    } else if (EPI == 5) {
        if (col < DD2) {
            *(__half2*)(Ch + (size_t)m * DD2 + col) =
                __halves2half2(__float2half(v0), __float2half(v1));
        } else {
            *(__half2*)(Ch2 + (size_t)m * DD2 + (col - DD2)) =
                __halves2half2(__float2half(siluf(v0)), __float2half(siluf(v1)));
        }
    } else {
        *(__half2*)(Ch + (size_t)m * ldc + col) =
            __halves2half2(__float2half(v0), __float2half(v1));
    }
}

// ---------------- pipelined chunk compute (NKS k-steps, NT<=4 n-tiles) -------
#define STA 0
#define STB 16384
#define STG_SZ 24576
#define SM_TOTAL (2*STG_SZ)

template<int NKS, int NT>
__device__ __forceinline__ void gemm_chunk(uint32_t base, const uint32_t* oa,
                                           const uint32_t* ob, float acc[2][4][4])
{
    if (NT == 0) return;
    constexpr int NP = (NT + 1) / 2;   // B fragments (2 n-tiles each), <=2
    const uint32_t a0 = base + oa[0], a1 = base + oa[1];
#pragma unroll
    for (int ks = 0; ks < NKS; ks++) {
        const uint32_t kx = (uint32_t)(ks * 32);
        uint32_t ah[2][4];
        ldsm4(ah[0], a0 ^ kx);
        ldsm4(ah[1], a1 ^ kx);
        uint32_t rb[4];
        ldsm4(rb, (base + ob[0]) ^ kx);
#pragma unroll
        for (int p = 0; p < NP; p++) {
            uint32_t rnx[4];
            if (p + 1 < NP) ldsm4(rnx, (base + ob[1]) ^ kx);
            uint32_t f0[2] = {rb[0], rb[1]}, f1[2] = {rb[2], rb[3]};
            mma16816(acc[0][2*p],   ah[0], f0);
            mma16816(acc[1][2*p],   ah[1], f0);
            if (2*p + 1 < NT) {
                mma16816(acc[0][2*p+1], ah[0], f1);
                mma16816(acc[1][2*p+1], ah[1], f1);
            }
            if (p + 1 < NP) { rb[0]=rnx[0]; rb[1]=rnx[1]; rb[2]=rnx[2]; rb[3]=rnx[3]; }
        }
    }
}

// ---------------- GEMM: C[M,NWTOT] = epi(A[M,KV] @ B[NWTOT,KV]^T + bias) -----
// CTA tile 128(M) x 64(N), 8 warps = 4M x 2N (warp 32x32), 2-stage cp.async,
// 4 CTAs/SM (192KB smem, 64 regs). NWTOT compile-time for exact N-trim.
template<int EPI, int KV, int NWTOT>
__global__ void __launch_bounds__(256, 4)
mma_gemm(const __half* __restrict__ A, const __half* __restrict__ B,
         const float* __restrict__ bias,
         float* Cf, __half* Ch, __half* Ch2,
         int M, int ldc)
{
    extern __shared__ char smem[];
    const uint32_t sb = sm2u32(smem);
    const int tid  = threadIdx.x;
    const int lane = tid & 31;
    const int wid  = tid >> 5;
    const int wm   = wid & 3;      // 0..3 (M, 32 rows each)
    const int wn   = wid >> 2;     // 0..1 (N, 32 cols each)
    const int m0   = blockIdx.y * 128;
    const int n0   = blockIdx.x * 64;

    constexpr int NFULL = NWTOT / 64;
    constexpr int NREM  = NWTOT % 64;           // multiple of 8
    constexpr int NT0   = NREM ? ((NREM >= 32) ? 4 : NREM / 8) : 4;
    constexpr int NT1   = (NREM > 32) ? (NREM - 32) / 8 : 0;

    const bool full = (NREM == 0) || ((int)blockIdx.x < NFULL);
    const int ntcnt = full ? 4 : (wn ? NT1 : NT0);

    float acc[2][4][4];
#pragma unroll
    for (int i = 0; i < 2; i++)
#pragma unroll
        for (int j = 0; j < 4; j++)
#pragma unroll
            for (int q = 0; q < 4; q++) acc[i][j][q] = 0.f;

    // per-thread swizzled fragment offsets (relative to stage base)
    uint32_t oa[2], ob[2];
    {
#pragma unroll
        for (int mt = 0; mt < 2; mt++) {
            int row = wm * 32 + mt * 16 + (lane & 15);
            oa[mt] = STA + SWZ((uint32_t)(row * 128 + (lane >> 4) * 16));
        }
        const int q    = lane >> 3;
        const int rowo = (q >> 1) * 8 + (lane & 7);
        const int ko   = (q & 1) * 8;
#pragma unroll
        for (int p = 0; p < 2; p++) {
            int row = wn * 32 + p * 16 + rowo;
            ob[p] = STB + SWZ((uint32_t)(row * 128 + ko * 2));
        }
    }

    constexpr int KST  = (KV + 15) >> 4;
    constexpr int KC   = (KST + 3) >> 2;
    constexpr int TAIL = KST - ((KST >> 2) << 2);
    constexpr int TK   = TAIL ? TAIL : 4;

    auto load_stage = [&](int stg, int k0) {
        uint32_t base = sb + stg * STG_SZ;
#pragma unroll
        for (int i = 0; i < 4; i++) {          // A: 128 rows x 64 k
            int idx = tid + i * 256;
            int r = idx >> 3, u = idx & 7;
            int gm = m0 + r, gk = k0 + u * 8;
            bool ok = (gm < M) && (gk < KV);
            size_t go = (size_t)(ok ? gm : 0) * KV + (ok ? gk : 0);
            cpa16(base + STA + SWZ(r * 128 + u * 16), A + go, ok ? 16u : 0u);
        }
#pragma unroll
        for (int i = 0; i < 2; i++) {          // B: 64 rows x 64 k
            int idx = tid + i * 256;
            int r = idx >> 3, u = idx & 7;
            int gn = n0 + r, gk = k0 + u * 8;
            bool ok = (gn < NWTOT) && (gk < KV);
            size_t go = (size_t)(ok ? gn : 0) * KV + (ok ? gk : 0);
            cpa16(base + STB + SWZ(r * 128 + u * 16), B + go, ok ? 16u : 0u);
        }
    };

    load_stage(0, 0);
    cp_commit();

    for (int c = 0; c < KC; c++) {
        if (c + 1 < KC) {
            load_stage((c + 1) & 1, (c + 1) << 6);
            cp_commit();
            cp_wait<1>();
        } else {
            cp_wait<0>();
        }
        __syncthreads();

        const uint32_t base = sb + (c & 1) * STG_SZ;
        const bool lastc = (TAIL != 0) && (c == KC - 1);
        if (full) {
            if (!lastc) gemm_chunk<4, 4>(base, oa, ob, acc);
            else        gemm_chunk<TK, 4>(base, oa, ob, acc);
        } else if (wn == 0) {
            if (!lastc) gemm_chunk<4, NT0>(base, oa, ob, acc);
            else        gemm_chunk<TK, NT0>(base, oa, ob, acc);
        } else {
            if (!lastc) gemm_chunk<4, NT1>(base, oa, ob, acc);
            else        gemm_chunk<TK, NT1>(base, oa, ob, acc);
        }
        __syncthreads();
    }

    // ---- epilogue (column bounds exact by construction) ----
    if (EPI == 6) {
#pragma unroll
        for (int mt = 0; mt < 2; mt++) {
            int r0 = m0 + wm * 32 + mt * 16 + (lane >> 2);
            int r1 = r0 + 8;
            float s0 = 0.f, s1 = 0.f;
#pragma unroll
            for (int nt = 0; nt < 4; nt++) {
                int col = n0 + wn * 32 + nt * 8 + (lane & 3) * 2;
                float b0 = bias[col], b1 = bias[col + 1];
                s0 += (acc[mt][nt][0] + b0) * (acc[mt][nt][1] + b1);
                s1 += (acc[mt][nt][2] + b0) * (acc[mt][nt][3] + b1);
            }
            if (r0 < M) atomicAdd(&g_s[r0], s0);
            if (r1 < M) atomicAdd(&g_s[r1], s1);
        }
    } else {
#pragma unroll
        for (int mt = 0; mt < 2; mt++) {
            int r0 = m0 + wm * 32 + mt * 16 + (lane >> 2);
            int r1 = r0 + 8;
#pragma unroll
            for (int nt = 0; nt < 4; nt++) {
                if (nt < ntcnt) {
                    int col = n0 + wn * 32 + nt * 8 + (lane & 3) * 2;
                    if (r0 < M) epi2<EPI>(r0, col, ldc, acc[mt][nt][0], acc[mt][nt][1], bias, Cf, Ch, Ch2);
                    if (r1 < M) epi2<EPI>(r1, col, ldc, acc[mt][nt][2], acc[mt][nt][3], bias, Cf, Ch, Ch2);
                }
            }
        }
    }
}

// ---------------- weight prep (ONE launch) -----------------------------------
#define SEG_CL  (DD2*DD2)
#define SEG_23  (256*DD2)
#define SEG_F1  (DD2*DD2)
#define SEG_OP  (DM*DD2)
#define SEG_ALL (SEG_CL+SEG_23+SEG_F1+SEG_OP)
#define R0_END  (NL*2*DD2*DM)
#define R1_END  (R0_END + NL*SEG_ALL)
#define R2_END  (R1_END + NL*2*DD2 + NL*256)

__global__ void wprep_all(const float* __restrict__ inw, const float* __restrict__ dww,
                          const float* __restrict__ cl, const float* __restrict__ f2,
                          const float* __restrict__ f3, const float* __restrict__ f1,
                          const float* __restrict__ op,
                          const float* __restrict__ inb, const float* __restrict__ db,
                          const float* __restrict__ f2b, const float* __restrict__ f3b)
{
    int idx = blockIdx.x * blockDim.x + threadIdx.x;
    if (idx < R0_END) {
        const int PER = 2 * DD2 * DM;
        int l = idx / PER, q = idx % PER;
        int n = q / DM, k = q % DM;
        float v = (n < DD2) ? inw[(size_t)l*DM*DD2 + k*DD2 + n]
                            : dww[(size_t)l*DM*DD2 + k*DD2 + (n - DD2)];
        g_wipdw[idx] = __float2half(v);
    } else if (idx < R1_END) {
        int t = idx - R0_END;
        int l = t / SEG_ALL, r = t % SEG_ALL;
        if (r < SEG_CL) {
            int n = r / DD2, k = r % DD2;
            g_wcl[(long)l*SEG_CL + r] = __float2half(cl[(size_t)l*SEG_CL + (size_t)k*DD2 + n]);
        } else if (r < SEG_CL + SEG_23) {
            int q = r - SEG_CL;
            int n = q / DD2, k = q % DD2;
            int j = n >> 1;
            float v = (n & 1) ? f3[(size_t)l*DD2*SSZ + (size_t)k*SSZ + j]
                              : f2[(size_t)l*DD2*SSZ + (size_t)k*SSZ + j];
            g_w23[(long)l*SEG_23 + q] = __float2half(v);
        } else if (r < SEG_CL + SEG_23 + SEG_F1) {
            int q = r - SEG_CL - SEG_23;
            int n = q / DD2, k = q % DD2;
            g_wf1[(long)l*SEG_F1 + q] = __float2half(f1[(size_t)l*SEG_F1 + (size_t)k*DD2 + n]);
        } else {
            int q = r - SEG_CL - SEG_23 - SEG_F1;
            int n = q / DD2, k = q % DD2;
            g_wop[(long)l*SEG_OP + q] = __float2half(op[(size_t)l*SEG_OP + (size_t)k*DM + n]);
        }
    } else if (idx < R2_END) {
        int t = idx - R1_END;
        const int N1 = NL * 2 * DD2;
        if (t < N1) {
            int l = t / (2*DD2), j = t % (2*DD2);
            g_bipdw[t] = (j < DD2) ? inb[l*DD2 + j] : db[l*DD2 + (j - DD2)];
        } else {
            int q = t - N1;
            int l = q / 256, j = q % 256;
            g_b23[q] = (j & 1) ? f3b[l*SSZ + (j >> 1)] : f2b[l*SSZ + (j >> 1)];
        }
    }
}

// ---------------- embedding (f32 h) ------------------------------------------
__global__ void embed_kernel(const float* __restrict__ x, const float* __restrict__ W_in,
                             const float* __restrict__ b_in, const float* __restrict__ tod,
                             const float* __restrict__ dow, const float* __restrict__ adp)
{
    long idx = blockIdx.x * (long)blockDim.x + threadIdx.x;
    if (idx >= (long)MTOK * DM) return;
    int  c      = (int)(idx % DM);
    long tokidx = idx / DM;
    int  t      = (int)(tokidx % T_);
    long rn     = tokidx / T_;
    int  n      = (int)(rn % NN_);
    int  b      = (int)(rn / NN_);
    const float* xe = x + (((long)(b * T_ + t) * NN_ + n) * 3);
    float v;
    if (c < 24) {
        v = b_in[c] + xe[0]*W_in[c] + xe[1]*W_in[24+c] + xe[2]*W_in[48+c];
    } else if (c < 48) {
        int ti = (int)(xe[1] * (float)STEPS);
        ti = min(max(ti, 0), STEPS - 1);
        v = tod[ti*24 + (c-24)];
    } else if (c < 72) {
        int di = (int)xe[2];
        di = min(max(di, 0), 6);
        v = dow[di*24 + (c-48)];
    } else {
        v = adp[((long)t * NN_ + n) * 80 + (c - 72)];
    }
    g_h[idx] = v;
}

// ---------------- rmsnorm (f32 in, fp16 out) ; zeroes g_s --------------------
__global__ void rmsnorm_kernel(const float* __restrict__ w)
{
    int gwarp = (blockIdx.x * blockDim.x + threadIdx.x) >> 5;
    int lane  = threadIdx.x & 31;
    if (gwarp >= MTOK) return;
    const float* row = g_h + (long)gwarp * DM;
    float ss = 0.f;
    for (int c = lane; c < DM; c += 32) { float v = row[c]; ss += v * v; }
#pragma unroll
    for (int o = 16; o; o >>= 1) ss += __shfl_xor_sync(0xffffffffu, ss, o);
    float scale = rsqrtf(ss / (float)DM + 1e-5f);
    long base = (long)gwarp * DM;
    for (int c = lane; c < DM; c += 32)
        g_xn[base + c] = __float2half(row[c] * scale * w[c]);
    if (!lane) g_s[gwarp] = 0.f;
}

// ---------------- conv over T + silu -> fp16 (warp-aligned shfl) -------------
#define DCHUNKS 10
__global__ void conv_silu_kernel(const float* __restrict__ cw, const float* __restrict__ cb)
{
    __shared__ float w[T_*T_*3];
    __shared__ float bsh[T_];
    for (int i = threadIdx.x; i < T_*T_*3; i += blockDim.x) w[i] = cw[i];
    for (int i = threadIdx.x; i < T_;      i += blockDim.x) bsh[i] = cb[i];
    __syncthreads();

    int gw = (int)((blockIdx.x * (long)blockDim.x + threadIdx.x) >> 5);
    if (gw >= ROWS * DCHUNKS) return;
    int lane = threadIdx.x & 31;
    int r  = gw / DCHUNKS;
    int dc = gw % DCHUNKS;
    int d  = dc * 32 + lane;
    int dl = min(d, DD2 - 1);
    const __half* xrow = g_xp + (long)r * (T_ * DD2);

    float v1[T_];
#pragma unroll
    for (int ti = 0; ti < T_; ti++) v1[ti] = __half2float(xrow[ti*DD2 + dl]);

    float acc[T_];
#pragma unroll
    for (int to = 0; to < T_; to++) acc[to] = bsh[to];

#pragma unroll
    for (int ti = 0; ti < T_; ti++) {
        float v0 = __shfl_up_sync(0xffffffffu, v1[ti], 1);
        float v2 = __shfl_down_sync(0xffffffffu, v1[ti], 1);
        if (lane == 0)  v0 = (d > 0) ? __half2float(xrow[ti*DD2 + d - 1]) : 0.f;
        if (lane == 31) v2 = (d < DD2 - 1) ? __half2float(xrow[ti*DD2 + d + 1]) : 0.f;
        if (d >= DD2 - 1) v2 = 0.f;
#pragma unroll
        for (int to = 0; to < T_; to++) {
            const float* wp = &w[(to*T_ + ti)*3];
            acc[to] += v0*wp[0] + v1[ti]*wp[1] + v2*wp[2];
        }
    }
    if (d < DD2) {
        long obase = (long)r * (T_ * DD2) + d;
#pragma unroll
        for (int to = 0; to < T_; to++)
            g_xca[obase + to*DD2] = __float2half(siluf(acc[to]));
    }
}

// ---------------- head: smem-cached W_out, 16 rows/block, f32 h --------------
#define OUTR 16
__global__ void out_kernel(const float* __restrict__ Wout, const float* __restrict__ bout,
                           float* __restrict__ out)
{
    extern __shared__ float ws[];   // [12][1824] transposed
    for (int i = threadIdx.x; i < T_*DM*12; i += 384) {
        int k = i / 12, j = i % 12;
        ws[j * (T_*DM) + k] = Wout[i];
    }
    __syncthreads();
    int wj   = threadIdx.x >> 5;    // 0..11
    int lane = threadIdx.x & 31;
    const float* wcol = ws + wj * (T_*DM);
    for (int rr = 0; rr < OUTR; rr++) {
        int rn = blockIdx.x * OUTR + rr;
        if (rn >= ROWS) break;
        const float4* row = (const float4*)(g_h + (long)rn * (T_*DM));
        float acc = 0.f;
        for (int k4 = lane; k4 < (T_*DM)/4; k4 += 32) {
            float4 hv = row[k4];
            acc += hv.x * wcol[4*k4] + hv.y * wcol[4*k4+1]
                 + hv.z * wcol[4*k4+2] + hv.w * wcol[4*k4+3];
        }
#pragma unroll
        for (int o = 16; o; o >>= 1) acc += __shfl_xor_sync(0xffffffffu, acc, o);
        if (!lane) {
            int n = rn % NN_, b = rn / NN_;
            out[((long)b * 12 + wj) * NN_ + n] = acc + bout[wj];
        }
    }
}

// =============================================================================
extern "C" void kernel_launch(void* const* d_in, const int* in_sizes, int n_in,
                              void* d_out, int out_size)
{
    (void)in_sizes; (void)n_in; (void)out_size;
    const float* x        = (const float*)d_in[0];
    const float* W_in     = (const float*)d_in[1];
    const float* b_in     = (const float*)d_in[2];
    const float* tod      = (const float*)d_in[3];
    const float* dow      = (const float*)d_in[4];
    const float* adp      = (const float*)d_in[5];
    const float* norm_w   = (const float*)d_in[6];
    const float* inproj_w = (const float*)d_in[7];
    const float* inproj_b = (const float*)d_in[8];
    const float* conv_w   = (const float*)d_in[9];
    const float* conv_b   = (const float*)d_in[10];
    const float* convlin_w= (const float*)d_in[11];
    const float* convlin_b= (const float*)d_in[12];
    const float* fc1_w    = (const float*)d_in[13];
    const float* fc1_b    = (const float*)d_in[14];
    const float* fc2_w    = (const float*)d_in[15];
    const float* fc2_b    = (const float*)d_in[16];
    const float* fc3_w    = (const float*)d_in[17];
    const float* fc3_b    = (const float*)d_in[18];
    /* d_in[19] = A_ssm unused (h0 == 0) */
    const float* D_w      = (const float*)d_in[20];
    const float* D_b      = (const float*)d_in[21];
    const float* outproj_w= (const float*)d_in[22];
    const float* outproj_b= (const float*)d_in[23];
    const float* W_out    = (const float*)d_in[24];
    const float* b_out    = (const float*)d_in[25];
    float* out = (float*)d_out;

    cudaFuncSetAttribute((const void*)mma_gemm<5,152,608>, cudaFuncAttributeMaxDynamicSharedMemorySize, SM_TOTAL);
    cudaFuncSetAttribute((const void*)mma_gemm<3,304,304>, cudaFuncAttributeMaxDynamicSharedMemorySize, SM_TOTAL);
    cudaFuncSetAttribute((const void*)mma_gemm<6,304,256>, cudaFuncAttributeMaxDynamicSharedMemorySize, SM_TOTAL);
    cudaFuncSetAttribute((const void*)mma_gemm<4,304,304>, cudaFuncAttributeMaxDynamicSharedMemorySize, SM_TOTAL);
    cudaFuncSetAttribute((const void*)mma_gemm<0,304,152>, cudaFuncAttributeMaxDynamicSharedMemorySize, SM_TOTAL);
    cudaFuncSetAttribute((const void*)out_kernel, cudaFuncAttributeMaxDynamicSharedMemorySize,
                         T_*DM*12*(int)sizeof(float));

    void* p;
#define SYM(sym, var, ty) cudaGetSymbolAddress(&p, sym); ty* var = (ty*)p;
    SYM(g_b23,   b23_p,  float)
    SYM(g_bipdw, bipdw_p,float)
    SYM(g_h,     h_p,    float)
    SYM(g_xn,    xn_p,   __half)
    SYM(g_xp,    xp_p,   __half)
    SYM(g_z,     z_p,    __half)
    SYM(g_xca,   xca_p,  __half)
    SYM(g_xco,   xco_p,  __half)
    SYM(g_cb,    cb_p,   __half)
    SYM(g_wipdw, wpd_p,  __half)
    SYM(g_wcl,   wcl_p,  __half)
    SYM(g_w23,   w23_p,  __half)
    SYM(g_wf1,   wf1_p,  __half)
    SYM(g_wop,   wop_p,  __half)
#undef SYM

    // launch 0: embedding
    {
        long tot = (long)MTOK * DM;
        embed_kernel<<<(int)((tot + 255)/256), 256>>>(x, W_in, b_in, tod, dow, adp);
    }
    // launch 1: rmsnorm layer 0
    rmsnorm_kernel<<<(MTOK*32 + 255)/256, 256>>>(norm_w);
    // launch 2: all weight prep
    wprep_all<<<(R2_END + 255)/256, 256>>>(inproj_w, D_w, convlin_w, fc2_w, fc3_w,
                                           fc1_w, outproj_w, inproj_b, D_b, fc2_b, fc3_b);

    for (int i = 0; i < NL; i++) {
        if (i > 0)
            rmsnorm_kernel<<<(MTOK*32 + 255)/256, 256>>>(norm_w + i*DM);

        // fused inproj|D_w : xn(152) -> xp(fp16) & z(fp16 silu), N=608
        mma_gemm<5,152,608><<<dim3(10, MTILES), 256, SM_TOTAL>>>(xn_p,
            wpd_p + (long)i*2*DD2*DM, bipdw_p + (long)i*2*DD2,
            nullptr, xp_p, z_p, MTOK, DD2);

        conv_silu_kernel<<<(ROWS*DCHUNKS*32 + 255)/256, 256>>>(conv_w + i*T_*T_*3, conv_b + i*T_);

        // convlin: xca(304) -> xco fp16(304)
        mma_gemm<3,304,304><<<dim3(5, MTILES), 256, SM_TOTAL>>>(xca_p,
            wcl_p + (long)i*DD2*DD2, convlin_b + i*DD2,
            nullptr, xco_p, nullptr, MTOK, DD2);

        // fc2|fc3 interleaved: epilogue computes s via pair products + atomics
        mma_gemm<6,304,256><<<dim3(4, MTILES), 256, SM_TOTAL>>>(xco_p,
            w23_p + (long)i*256*DD2, b23_p + i*256,
            nullptr, nullptr, nullptr, MTOK, 256);

        // fc1 + combine fused: -> cb fp16(304)
        mma_gemm<4,304,304><<<dim3(5, MTILES), 256, SM_TOTAL>>>(xco_p,
            wf1_p + (long)i*DD2*DD2, fc1_b + i*DD2,
            nullptr, cb_p, nullptr, MTOK, DD2);

        // outproj: cb(304) -> h f32(152)
        mma_gemm<0,304,152><<<dim3(3, MTILES), 256, SM_TOTAL>>>(cb_p,
            wop_p + (long)i*DM*DD2, outproj_b + i*DM,
            h_p, nullptr, nullptr, MTOK, DM);
    }

    out_kernel<<<(ROWS + OUTR - 1)/OUTR, 384, T_*DM*12*sizeof(float)>>>(W_out, b_out, out);
}

// round 16
// speedup vs baseline: 1.1985x; 1.0416x over previous
#include <cuda_runtime.h>
#include <cuda_fp16.h>
#include <math.h>
#include <stdint.h>

#define B_    8
#define T_    12
#define NN_   883
#define DM    152
#define DD2   304
#define SSZ   128
#define NL    3
#define STEPS 288
#define ROWS  (B_*NN_)          /* 7064  */
#define MTOK  (ROWS*T_)         /* 84768 */
#define MTILES ((MTOK+127)/128) /* 663   */

// ---------------- scratch (device globals; no allocs allowed) ----------------
__device__ float  g_s [MTOK];
__device__ float  g_h [MTOK*DM];
__device__ __half g_xn [MTOK*DM];
__device__ __half g_xp [MTOK*DD2];
__device__ __half g_z  [MTOK*DD2];
__device__ __half g_xca[MTOK*DD2];
__device__ __half g_xco[MTOK*DD2];
__device__ __half g_cb [MTOK*DD2];

// transposed fp16 weights: [N rows, K cols]
__device__ __half g_wipdw[NL*2*DD2*DM];   /* 608 x 152 */
__device__ __half g_wcl  [NL*DD2*DD2];
__device__ __half g_w23  [NL*256*DD2];    /* interleaved: row 2j=fc2_j, 2j+1=fc3_j */
__device__ __half g_wf1  [NL*DD2*DD2];
__device__ __half g_wop  [NL*DM*DD2];
__device__ float  g_b23  [NL*256];
__device__ float  g_bipdw[NL*2*DD2];

__device__ __forceinline__ float siluf(float v)     { return v / (1.f + expf(-v)); }
__device__ __forceinline__ float softplusf(float v) { return (v > 20.f) ? v : log1pf(expf(v)); }

__device__ __forceinline__ uint32_t sm2u32(const void* p) {
    uint32_t a;
    asm("{ .reg .u64 t; cvta.to.shared.u64 t, %1; cvt.u32.u64 %0, t; }" : "=r"(a) : "l"(p));
    return a;
}
#define SWZ(o) ((uint32_t)(o) ^ ((((uint32_t)(o)) >> 3) & 0x70u))

__device__ __forceinline__ void ldsm4(uint32_t* r, uint32_t addr) {
    asm volatile("ldmatrix.sync.aligned.m8n8.x4.shared.b16 {%0,%1,%2,%3}, [%4];"
                 : "=r"(r[0]), "=r"(r[1]), "=r"(r[2]), "=r"(r[3]) : "r"(addr));
}
__device__ __forceinline__ void mma16816(float* c, const uint32_t* a, const uint32_t* b) {
    asm("mma.sync.aligned.m16n8k16.row.col.f32.f16.f16.f32 "
        "{%0,%1,%2,%3}, {%4,%5,%6,%7}, {%8,%9}, {%0,%1,%2,%3};"
        : "+f"(c[0]), "+f"(c[1]), "+f"(c[2]), "+f"(c[3])
        : "r"(a[0]), "r"(a[1]), "r"(a[2]), "r"(a[3]), "r"(b[0]), "r"(b[1]));
}
__device__ __forceinline__ void cpa16(uint32_t dst, const void* src, uint32_t sz) {
    asm volatile("cp.async.cg.shared.global [%0], [%1], 16, %2;"
                 :: "r"(dst), "l"(src), "r"(sz) : "memory");
}
__device__ __forceinline__ void cp_commit() {
    asm volatile("cp.async.commit_group;" ::: "memory");
}
template<int N>
__device__ __forceinline__ void cp_wait() {
    asm volatile("cp.async.wait_group %0;" :: "n"(N) : "memory");
}

// ---------------- fused epilogue -------------------------------------------
// EPI: 0 bias->f32 | 3 bias->fp16 | 4 fc1+combine->fp16
//      5 dual fp16: col<DD2 -> xp ; col>=DD2 -> silu -> z
//      6 inline in GEMM (BC pair-product -> atomic s)
template<int EPI>
__device__ __forceinline__ void epi2(int m, int col, int ldc, float v0, float v1,
    const float* __restrict__ bias, float* Cf, __half* Ch, __half* Ch2)
{
    v0 += bias[col]; v1 += bias[col + 1];
    if (EPI == 4) {
        float sv = g_s[m];
        size_t off = (size_t)m * DD2 + col;
        float xc0 = __half2float(g_xco[off]);
        float xc1 = __half2float(g_xco[off + 1]);
        v0 = siluf(xc0 * softplusf(v0) * sv) * __half2float(g_z[off]);
        v1 = siluf(xc1 * softplusf(v1) * sv) * __half2float(g_z[off + 1]);
    }
    if (EPI == 0) {
        *(float2*)(Cf + (size_t)m * ldc + col) = make_float2(v0, v1);
    } else if (EPI == 5) {
        if (col < DD2) {
            *(__half2*)(Ch + (size_t)m * DD2 + col) =
                __halves2half2(__float2half(v0), __float2half(v1));
        } else {
            *(__half2*)(Ch2 + (size_t)m * DD2 + (col - DD2)) =
                __halves2half2(__float2half(siluf(v0)), __float2half(siluf(v1)));
        }
    } else {
        *(__half2*)(Ch + (size_t)m * ldc + col) =
            __halves2half2(__float2half(v0), __float2half(v1));
    }
}

// ---------------- pipelined chunk compute (NKS k-steps, NT<=4 n-tiles) -------
#define STA 0
#define STB 16384
#define STG_SZ 24576
#define SM_TOTAL (2*STG_SZ)

template<int NKS, int NT>
__device__ __forceinline__ void gemm_chunk(uint32_t base, const uint32_t* oa,
                                           const uint32_t* ob, float acc[2][4][4])
{
    if (NT == 0) return;
    constexpr int NP = (NT + 1) / 2;   // B fragments (2 n-tiles each), <=2
    const uint32_t a0 = base + oa[0], a1 = base + oa[1];
#pragma unroll
    for (int ks = 0; ks < NKS; ks++) {
        const uint32_t kx = (uint32_t)(ks * 32);
        uint32_t ah[2][4];
        ldsm4(ah[0], a0 ^ kx);
        ldsm4(ah[1], a1 ^ kx);
        uint32_t rb[4];
        ldsm4(rb, (base + ob[0]) ^ kx);
#pragma unroll
        for (int p = 0; p < NP; p++) {
            uint32_t rnx[4];
            if (p + 1 < NP) ldsm4(rnx, (base + ob[1]) ^ kx);
            uint32_t f0[2] = {rb[0], rb[1]}, f1[2] = {rb[2], rb[3]};
            mma16816(acc[0][2*p],   ah[0], f0);
            mma16816(acc[1][2*p],   ah[1], f0);
            if (2*p + 1 < NT) {
                mma16816(acc[0][2*p+1], ah[0], f1);
                mma16816(acc[1][2*p+1], ah[1], f1);
            }
            if (p + 1 < NP) { rb[0]=rnx[0]; rb[1]=rnx[1]; rb[2]=rnx[2]; rb[3]=rnx[3]; }
        }
    }
}

// ---------------- GEMM: C[M,NWTOT] = epi(A[M,KV] @ B[NWTOT,KV]^T + bias) -----
// CTA tile 128(M) x 64(N), 8 warps = 4M x 2N (warp 32x32), 2-stage cp.async,
// 4 CTAs/SM (192KB smem, 64 regs). NWTOT compile-time for exact N-trim.
template<int EPI, int KV, int NWTOT>
__global__ void __launch_bounds__(256, 4)
mma_gemm(const __half* __restrict__ A, const __half* __restrict__ B,
         const float* __restrict__ bias,
         float* Cf, __half* Ch, __half* Ch2,
         int M, int ldc)
{
    extern __shared__ char smem[];
    const uint32_t sb = sm2u32(smem);
    const int tid  = threadIdx.x;
    const int lane = tid & 31;
    const int wid  = tid >> 5;
    const int wm   = wid & 3;      // 0..3 (M, 32 rows each)
    const int wn   = wid >> 2;     // 0..1 (N, 32 cols each)
    const int m0   = blockIdx.y * 128;
    const int n0   = blockIdx.x * 64;

    constexpr int NFULL = NWTOT / 64;
    constexpr int NREM  = NWTOT % 64;           // multiple of 8
    constexpr int NT0   = NREM ? ((NREM >= 32) ? 4 : NREM / 8) : 4;
    constexpr int NT1   = (NREM > 32) ? (NREM - 32) / 8 : 0;

    const bool full = (NREM == 0) || ((int)blockIdx.x < NFULL);
    const int ntcnt = full ? 4 : (wn ? NT1 : NT0);

    float acc[2][4][4];
#pragma unroll
    for (int i = 0; i < 2; i++)
#pragma unroll
        for (int j = 0; j < 4; j++)
#pragma unroll
            for (int q = 0; q < 4; q++) acc[i][j][q] = 0.f;

    // per-thread swizzled fragment offsets (relative to stage base)
    uint32_t oa[2], ob[2];
    {
#pragma unroll
        for (int mt = 0; mt < 2; mt++) {
            int row = wm * 32 + mt * 16 + (lane & 15);
            oa[mt] = STA + SWZ((uint32_t)(row * 128 + (lane >> 4) * 16));
        }
        const int q    = lane >> 3;
        const int rowo = (q >> 1) * 8 + (lane & 7);
        const int ko   = (q & 1) * 8;
#pragma unroll
        for (int p = 0; p < 2; p++) {
            int row = wn * 32 + p * 16 + rowo;
            ob[p] = STB + SWZ((uint32_t)(row * 128 + ko * 2));
        }
    }

    constexpr int KST  = (KV + 15) >> 4;
    constexpr int KC   = (KST + 3) >> 2;
    constexpr int TAIL = KST - ((KST >> 2) << 2);
    constexpr int TK   = TAIL ? TAIL : 4;

    auto load_stage = [&](int stg, int k0) {
        uint32_t base = sb + stg * STG_SZ;
#pragma unroll
        for (int i = 0; i < 4; i++) {          // A: 128 rows x 64 k
            int idx = tid + i * 256;
            int r = idx >> 3, u = idx & 7;
            int gm = m0 + r, gk = k0 + u * 8;
            bool ok = (gm < M) && (gk < KV);
            size_t go = (size_t)(ok ? gm : 0) * KV + (ok ? gk : 0);
            cpa16(base + STA + SWZ(r * 128 + u * 16), A + go, ok ? 16u : 0u);
        }
#pragma unroll
        for (int i = 0; i < 2; i++) {          // B: 64 rows x 64 k
            int idx = tid + i * 256;
            int r = idx >> 3, u = idx & 7;
            int gn = n0 + r, gk = k0 + u * 8;
            bool ok = (gn < NWTOT) && (gk < KV);
            size_t go = (size_t)(ok ? gn : 0) * KV + (ok ? gk : 0);
            cpa16(base + STB + SWZ(r * 128 + u * 16), B + go, ok ? 16u : 0u);
        }
    };

    load_stage(0, 0);
    cp_commit();

    for (int c = 0; c < KC; c++) {
        if (c + 1 < KC) {
            load_stage((c + 1) & 1, (c + 1) << 6);
            cp_commit();
            cp_wait<1>();
        } else {
            cp_wait<0>();
        }
        __syncthreads();

        const uint32_t base = sb + (c & 1) * STG_SZ;
        const bool lastc = (TAIL != 0) && (c == KC - 1);
        if (full) {
            if (!lastc) gemm_chunk<4, 4>(base, oa, ob, acc);
            else        gemm_chunk<TK, 4>(base, oa, ob, acc);
        } else if (wn == 0) {
            if (!lastc) gemm_chunk<4, NT0>(base, oa, ob, acc);
            else        gemm_chunk<TK, NT0>(base, oa, ob, acc);
        } else {
            if (!lastc) gemm_chunk<4, NT1>(base, oa, ob, acc);
            else        gemm_chunk<TK, NT1>(base, oa, ob, acc);
        }
        __syncthreads();
    }

    // ---- epilogue (column bounds exact by construction) ----
    if (EPI == 6) {
#pragma unroll
        for (int mt = 0; mt < 2; mt++) {
            int r0 = m0 + wm * 32 + mt * 16 + (lane >> 2);
            int r1 = r0 + 8;
            float s0 = 0.f, s1 = 0.f;
#pragma unroll
            for (int nt = 0; nt < 4; nt++) {
                int col = n0 + wn * 32 + nt * 8 + (lane & 3) * 2;
                float b0 = bias[col], b1 = bias[col + 1];
                s0 += (acc[mt][nt][0] + b0) * (acc[mt][nt][1] + b1);
                s1 += (acc[mt][nt][2] + b0) * (acc[mt][nt][3] + b1);
            }
            if (r0 < M) atomicAdd(&g_s[r0], s0);
            if (r1 < M) atomicAdd(&g_s[r1], s1);
        }
    } else {
#pragma unroll
        for (int mt = 0; mt < 2; mt++) {
            int r0 = m0 + wm * 32 + mt * 16 + (lane >> 2);
            int r1 = r0 + 8;
#pragma unroll
            for (int nt = 0; nt < 4; nt++) {
                if (nt < ntcnt) {
                    int col = n0 + wn * 32 + nt * 8 + (lane & 3) * 2;
                    if (r0 < M) epi2<EPI>(r0, col, ldc, acc[mt][nt][0], acc[mt][nt][1], bias, Cf, Ch, Ch2);
                    if (r1 < M) epi2<EPI>(r1, col, ldc, acc[mt][nt][2], acc[mt][nt][3], bias, Cf, Ch, Ch2);
                }
            }
        }
    }
}

// ---------------- weight prep (ONE launch) -----------------------------------
#define SEG_CL  (DD2*DD2)
#define SEG_23  (256*DD2)
#define SEG_F1  (DD2*DD2)
#define SEG_OP  (DM*DD2)
#define SEG_ALL (SEG_CL+SEG_23+SEG_F1+SEG_OP)
#define R0_END  (NL*2*DD2*DM)
#define R1_END  (R0_END + NL*SEG_ALL)
#define R2_END  (R1_END + NL*2*DD2 + NL*256)

__global__ void wprep_all(const float* __restrict__ inw, const float* __restrict__ dww,
                          const float* __restrict__ cl, const float* __restrict__ f2,
                          const float* __restrict__ f3, const float* __restrict__ f1,
                          const float* __restrict__ op,
                          const float* __restrict__ inb, const float* __restrict__ db,
                          const float* __restrict__ f2b, const float* __restrict__ f3b)
{
    int idx = blockIdx.x * blockDim.x + threadIdx.x;
    if (idx < R0_END) {
        const int PER = 2 * DD2 * DM;
        int l = idx / PER, q = idx % PER;
        int n = q / DM, k = q % DM;
        float v = (n < DD2) ? inw[(size_t)l*DM*DD2 + k*DD2 + n]
                            : dww[(size_t)l*DM*DD2 + k*DD2 + (n - DD2)];
        g_wipdw[idx] = __float2half(v);
    } else if (idx < R1_END) {
        int t = idx - R0_END;
        int l = t / SEG_ALL, r = t % SEG_ALL;
        if (r < SEG_CL) {
            int n = r / DD2, k = r % DD2;
            g_wcl[(long)l*SEG_CL + r] = __float2half(cl[(size_t)l*SEG_CL + (size_t)k*DD2 + n]);
        } else if (r < SEG_CL + SEG_23) {
            int q = r - SEG_CL;
            int n = q / DD2, k = q % DD2;
            int j = n >> 1;
            float v = (n & 1) ? f3[(size_t)l*DD2*SSZ + (size_t)k*SSZ + j]
                              : f2[(size_t)l*DD2*SSZ + (size_t)k*SSZ + j];
            g_w23[(long)l*SEG_23 + q] = __float2half(v);
        } else if (r < SEG_CL + SEG_23 + SEG_F1) {
            int q = r - SEG_CL - SEG_23;
            int n = q / DD2, k = q % DD2;
            g_wf1[(long)l*SEG_F1 + q] = __float2half(f1[(size_t)l*SEG_F1 + (size_t)k*DD2 + n]);
        } else {
            int q = r - SEG_CL - SEG_23 - SEG_F1;
            int n = q / DD2, k = q % DD2;
            g_wop[(long)l*SEG_OP + q] = __float2half(op[(size_t)l*SEG_OP + (size_t)k*DM + n]);
        }
    } else if (idx < R2_END) {
        int t = idx - R1_END;
        const int N1 = NL * 2 * DD2;
        if (t < N1) {
            int l = t / (2*DD2), j = t % (2*DD2);
            g_bipdw[t] = (j < DD2) ? inb[l*DD2 + j] : db[l*DD2 + (j - DD2)];
        } else {
            int q = t - N1;
            int l = q / 256, j = q % 256;
            g_b23[q] = (j & 1) ? f3b[l*SSZ + (j >> 1)] : f2b[l*SSZ + (j >> 1)];
        }
    }
}

// ---------------- fused embedding + layer-0 rmsnorm (warp per token) ---------
// Computes all 152 features in registers, does the rms reduce via shfl, and
// writes g_h (f32, for residual) + g_xn (fp16) in one pass. Zeroes g_s.
__global__ void embed_rms_kernel(const float* __restrict__ x, const float* __restrict__ W_in,
                                 const float* __restrict__ b_in, const float* __restrict__ tod,
                                 const float* __restrict__ dow, const float* __restrict__ adp,
                                 const float* __restrict__ nw)
{
    int gwarp = (blockIdx.x * blockDim.x + threadIdx.x) >> 5;
    int lane  = threadIdx.x & 31;
    if (gwarp >= MTOK) return;

    int  t  = gwarp % T_;
    long rn = gwarp / T_;
    int  n  = (int)(rn % NN_);
    int  b  = (int)(rn / NN_);
    const float* xe = x + (((long)(b * T_ + t) * NN_ + n) * 3);
    float e0 = xe[0], e1 = xe[1], e2 = xe[2];
    int ti = (int)(e1 * (float)STEPS); ti = min(max(ti, 0), STEPS - 1);
    int di = (int)e2;                  di = min(max(di, 0), 6);

    float v[5];
    float ss = 0.f;
#pragma unroll
    for (int u = 0; u < 5; u++) {
        int c = lane + u * 32;
        float val = 0.f;
        if (c < DM) {
            if (c < 24)      val = b_in[c] + e0*W_in[c] + e1*W_in[24+c] + e2*W_in[48+c];
            else if (c < 48) val = tod[ti*24 + (c-24)];
            else if (c < 72) val = dow[di*24 + (c-48)];
            else             val = adp[((long)t * NN_ + n) * 80 + (c - 72)];
            ss += val * val;
        }
        v[u] = val;
    }
#pragma unroll
    for (int o = 16; o; o >>= 1) ss += __shfl_xor_sync(0xffffffffu, ss, o);
    float scale = rsqrtf(ss / (float)DM + 1e-5f);

    long base = (long)gwarp * DM;
#pragma unroll
    for (int u = 0; u < 5; u++) {
        int c = lane + u * 32;
        if (c < DM) {
            g_h [base + c] = v[u];
            g_xn[base + c] = __float2half(v[u] * scale * nw[c]);
        }
    }
    if (!lane) g_s[gwarp] = 0.f;
}

// ---------------- rmsnorm (f32 in, fp16 out) ; zeroes g_s --------------------
__global__ void rmsnorm_kernel(const float* __restrict__ w)
{
    int gwarp = (blockIdx.x * blockDim.x + threadIdx.x) >> 5;
    int lane  = threadIdx.x & 31;
    if (gwarp >= MTOK) return;
    const float* row = g_h + (long)gwarp * DM;
    float v[5];
    float ss = 0.f;
#pragma unroll
    for (int u = 0; u < 5; u++) {
        int c = lane + u * 32;
        float val = (c < DM) ? row[c] : 0.f;
        ss += val * val;
        v[u] = val;
    }
#pragma unroll
    for (int o = 16; o; o >>= 1) ss += __shfl_xor_sync(0xffffffffu, ss, o);
    float scale = rsqrtf(ss / (float)DM + 1e-5f);
    long base = (long)gwarp * DM;
#pragma unroll
    for (int u = 0; u < 5; u++) {
        int c = lane + u * 32;
        if (c < DM) g_xn[base + c] = __float2half(v[u] * scale * w[c]);
    }
    if (!lane) g_s[gwarp] = 0.f;
}

// ---------------- conv over T + silu -> fp16 (warp-aligned shfl) -------------
#define DCHUNKS 10
__global__ void conv_silu_kernel(const float* __restrict__ cw, const float* __restrict__ cb)
{
    __shared__ float w[T_*T_*3];
    __shared__ float bsh[T_];
    for (int i = threadIdx.x; i < T_*T_*3; i += blockDim.x) w[i] = cw[i];
    for (int i = threadIdx.x; i < T_;      i += blockDim.x) bsh[i] = cb[i];
    __syncthreads();

    int gw = (int)((blockIdx.x * (long)blockDim.x + threadIdx.x) >> 5);
    if (gw >= ROWS * DCHUNKS) return;
    int lane = threadIdx.x & 31;
    int r  = gw / DCHUNKS;
    int dc = gw % DCHUNKS;
    int d  = dc * 32 + lane;
    int dl = min(d, DD2 - 1);
    const __half* xrow = g_xp + (long)r * (T_ * DD2);

    float v1[T_];
#pragma unroll
    for (int ti = 0; ti < T_; ti++) v1[ti] = __half2float(xrow[ti*DD2 + dl]);

    float acc[T_];
#pragma unroll
    for (int to = 0; to < T_; to++) acc[to] = bsh[to];

#pragma unroll
    for (int ti = 0; ti < T_; ti++) {
        float v0 = __shfl_up_sync(0xffffffffu, v1[ti], 1);
        float v2 = __shfl_down_sync(0xffffffffu, v1[ti], 1);
        if (lane == 0)  v0 = (d > 0) ? __half2float(xrow[ti*DD2 + d - 1]) : 0.f;
        if (lane == 31) v2 = (d < DD2 - 1) ? __half2float(xrow[ti*DD2 + d + 1]) : 0.f;
        if (d >= DD2 - 1) v2 = 0.f;
#pragma unroll
        for (int to = 0; to < T_; to++) {
            const float* wp = &w[(to*T_ + ti)*3];
            acc[to] += v0*wp[0] + v1[ti]*wp[1] + v2*wp[2];
        }
    }
    if (d < DD2) {
        long obase = (long)r * (T_ * DD2) + d;
#pragma unroll
        for (int to = 0; to < T_; to++)
            g_xca[obase + to*DD2] = __float2half(siluf(acc[to]));
    }
}

// ---------------- head: smem-cached W_out, 16 rows/block, f32 h --------------
#define OUTR 16
__global__ void out_kernel(const float* __restrict__ Wout, const float* __restrict__ bout,
                           float* __restrict__ out)
{
    extern __shared__ float ws[];   // [12][1824] transposed
    for (int i = threadIdx.x; i < T_*DM*12; i += 384) {
        int k = i / 12, j = i % 12;
        ws[j * (T_*DM) + k] = Wout[i];
    }
    __syncthreads();
    int wj   = threadIdx.x >> 5;    // 0..11
    int lane = threadIdx.x & 31;
    const float* wcol = ws + wj * (T_*DM);
    for (int rr = 0; rr < OUTR; rr++) {
        int rn = blockIdx.x * OUTR + rr;
        if (rn >= ROWS) break;
        const float4* row = (const float4*)(g_h + (long)rn * (T_*DM));
        float acc = 0.f;
        for (int k4 = lane; k4 < (T_*DM)/4; k4 += 32) {
            float4 hv = row[k4];
            acc += hv.x * wcol[4*k4] + hv.y * wcol[4*k4+1]
                 + hv.z * wcol[4*k4+2] + hv.w * wcol[4*k4+3];
        }
#pragma unroll
        for (int o = 16; o; o >>= 1) acc += __shfl_xor_sync(0xffffffffu, acc, o);
        if (!lane) {
            int n = rn % NN_, b = rn / NN_;
            out[((long)b * 12 + wj) * NN_ + n] = acc + bout[wj];
        }
    }
}

// =============================================================================
extern "C" void kernel_launch(void* const* d_in, const int* in_sizes, int n_in,
                              void* d_out, int out_size)
{
    (void)in_sizes; (void)n_in; (void)out_size;
    const float* x        = (const float*)d_in[0];
    const float* W_in     = (const float*)d_in[1];
    const float* b_in     = (const float*)d_in[2];
    const float* tod      = (const float*)d_in[3];
    const float* dow      = (const float*)d_in[4];
    const float* adp      = (const float*)d_in[5];
    const float* norm_w   = (const float*)d_in[6];
    const float* inproj_w = (const float*)d_in[7];
    const float* inproj_b = (const float*)d_in[8];
    const float* conv_w   = (const float*)d_in[9];
    const float* conv_b   = (const float*)d_in[10];
    const float* convlin_w= (const float*)d_in[11];
    const float* convlin_b= (const float*)d_in[12];
    const float* fc1_w    = (const float*)d_in[13];
    const float* fc1_b    = (const float*)d_in[14];
    const float* fc2_w    = (const float*)d_in[15];
    const float* fc2_b    = (const float*)d_in[16];
    const float* fc3_w    = (const float*)d_in[17];
    const float* fc3_b    = (const float*)d_in[18];
    /* d_in[19] = A_ssm unused (h0 == 0) */
    const float* D_w      = (const float*)d_in[20];
    const float* D_b      = (const float*)d_in[21];
    const float* outproj_w= (const float*)d_in[22];
    const float* outproj_b= (const float*)d_in[23];
    const float* W_out    = (const float*)d_in[24];
    const float* b_out    = (const float*)d_in[25];
    float* out = (float*)d_out;

    cudaFuncSetAttribute((const void*)mma_gemm<5,152,608>, cudaFuncAttributeMaxDynamicSharedMemorySize, SM_TOTAL);
    cudaFuncSetAttribute((const void*)mma_gemm<3,304,304>, cudaFuncAttributeMaxDynamicSharedMemorySize, SM_TOTAL);
    cudaFuncSetAttribute((const void*)mma_gemm<6,304,256>, cudaFuncAttributeMaxDynamicSharedMemorySize, SM_TOTAL);
    cudaFuncSetAttribute((const void*)mma_gemm<4,304,304>, cudaFuncAttributeMaxDynamicSharedMemorySize, SM_TOTAL);
    cudaFuncSetAttribute((const void*)mma_gemm<0,304,152>, cudaFuncAttributeMaxDynamicSharedMemorySize, SM_TOTAL);
    cudaFuncSetAttribute((const void*)out_kernel, cudaFuncAttributeMaxDynamicSharedMemorySize,
                         T_*DM*12*(int)sizeof(float));

    void* p;
#define SYM(sym, var, ty) cudaGetSymbolAddress(&p, sym); ty* var = (ty*)p;
    SYM(g_b23,   b23_p,  float)
    SYM(g_bipdw, bipdw_p,float)
    SYM(g_h,     h_p,    float)
    SYM(g_xn,    xn_p,   __half)
    SYM(g_xp,    xp_p,   __half)
    SYM(g_z,     z_p,    __half)
    SYM(g_xca,   xca_p,  __half)
    SYM(g_xco,   xco_p,  __half)
    SYM(g_cb,    cb_p,   __half)
    SYM(g_wipdw, wpd_p,  __half)
    SYM(g_wcl,   wcl_p,  __half)
    SYM(g_w23,   w23_p,  __half)
    SYM(g_wf1,   wf1_p,  __half)
    SYM(g_wop,   wop_p,  __half)
#undef SYM

    // launch 0: fused embedding + layer-0 rmsnorm
    embed_rms_kernel<<<(MTOK*32 + 255)/256, 256>>>(x, W_in, b_in, tod, dow, adp, norm_w);
    // launch 1: all weight prep
    wprep_all<<<(R2_END + 255)/256, 256>>>(inproj_w, D_w, convlin_w, fc2_w, fc3_w,
                                           fc1_w, outproj_w, inproj_b, D_b, fc2_b, fc3_b);

    for (int i = 0; i < NL; i++) {
        if (i > 0)
            rmsnorm_kernel<<<(MTOK*32 + 255)/256, 256>>>(norm_w + i*DM);

        // fused inproj|D_w : xn(152) -> xp(fp16) & z(fp16 silu), N=608
        mma_gemm<5,152,608><<<dim3(10, MTILES), 256, SM_TOTAL>>>(xn_p,
            wpd_p + (long)i*2*DD2*DM, bipdw_p + (long)i*2*DD2,
            nullptr, xp_p, z_p, MTOK, DD2);

        conv_silu_kernel<<<(ROWS*DCHUNKS*32 + 255)/256, 256>>>(conv_w + i*T_*T_*3, conv_b + i*T_);

        // convlin: xca(304) -> xco fp16(304)
        mma_gemm<3,304,304><<<dim3(5, MTILES), 256, SM_TOTAL>>>(xca_p,
            wcl_p + (long)i*DD2*DD2, convlin_b + i*DD2,
            nullptr, xco_p, nullptr, MTOK, DD2);

        // fc2|fc3 interleaved: epilogue computes s via pair products + atomics
        mma_gemm<6,304,256><<<dim3(4, MTILES), 256, SM_TOTAL>>>(xco_p,
            w23_p + (long)i*256*DD2, b23_p + i*256,
            nullptr, nullptr, nullptr, MTOK, 256);

        // fc1 + combine fused: -> cb fp16(304)
        mma_gemm<4,304,304><<<dim3(5, MTILES), 256, SM_TOTAL>>>(xco_p,
            wf1_p + (long)i*DD2*DD2, fc1_b + i*DD2,
            nullptr, cb_p, nullptr, MTOK, DD2);

        // outproj: cb(304) -> h f32(152)
        mma_gemm<0,304,152><<<dim3(3, MTILES), 256, SM_TOTAL>>>(cb_p,
            wop_p + (long)i*DM*DD2, outproj_b + i*DM,
            h_p, nullptr, nullptr, MTOK, DM);
    }

    out_kernel<<<(ROWS + OUTR - 1)/OUTR, 384, T_*DM*12*sizeof(float)>>>(W_out, b_out, out);
}

// round 17
// speedup vs baseline: 1.2665x; 1.0568x over previous
#include <cuda_runtime.h>
#include <cuda_fp16.h>
#include <math.h>
#include <stdint.h>

#define B_    8
#define T_    12
#define NN_   883
#define DM    152
#define DD2   304
#define SSZ   128
#define NL    3
#define STEPS 288
#define ROWS  (B_*NN_)          /* 7064  */
#define MTOK  (ROWS*T_)         /* 84768 */
#define MTILES ((MTOK+127)/128) /* 663   */

// ---------------- scratch (device globals; no allocs allowed) ----------------
__device__ float  g_s [MTOK];
__device__ float  g_h [MTOK*DM];
__device__ __half g_xn [MTOK*DM];
__device__ __half g_xp [MTOK*DD2];
__device__ __half g_z  [MTOK*DD2];
__device__ __half g_xca[MTOK*DD2];
__device__ __half g_xco[MTOK*DD2];
__device__ __half g_cb [MTOK*DD2];

// transposed fp16 weights: [N rows, K cols]
__device__ __half g_wipdw[NL*2*DD2*DM];   /* 608 x 152 */
__device__ __half g_wcl  [NL*DD2*DD2];
__device__ __half g_w23  [NL*256*DD2];    /* interleaved: row 2j=fc2_j, 2j+1=fc3_j */
__device__ __half g_wf1  [NL*DD2*DD2];
__device__ __half g_wop  [NL*DM*DD2];
__device__ float  g_b23  [NL*256];
__device__ float  g_bipdw[NL*2*DD2];

__device__ __forceinline__ float siluf(float v)     { return v / (1.f + expf(-v)); }
__device__ __forceinline__ float softplusf(float v) { return (v > 20.f) ? v : log1pf(expf(v)); }

__device__ __forceinline__ uint32_t sm2u32(const void* p) {
    uint32_t a;
    asm("{ .reg .u64 t; cvta.to.shared.u64 t, %1; cvt.u32.u64 %0, t; }" : "=r"(a) : "l"(p));
    return a;
}
#define SWZ(o) ((uint32_t)(o) ^ ((((uint32_t)(o)) >> 3) & 0x70u))

__device__ __forceinline__ void ldsm4(uint32_t* r, uint32_t addr) {
    asm volatile("ldmatrix.sync.aligned.m8n8.x4.shared.b16 {%0,%1,%2,%3}, [%4];"
                 : "=r"(r[0]), "=r"(r[1]), "=r"(r[2]), "=r"(r[3]) : "r"(addr));
}
__device__ __forceinline__ void mma16816(float* c, const uint32_t* a, const uint32_t* b) {
    asm("mma.sync.aligned.m16n8k16.row.col.f32.f16.f16.f32 "
        "{%0,%1,%2,%3}, {%4,%5,%6,%7}, {%8,%9}, {%0,%1,%2,%3};"
        : "+f"(c[0]), "+f"(c[1]), "+f"(c[2]), "+f"(c[3])
        : "r"(a[0]), "r"(a[1]), "r"(a[2]), "r"(a[3]), "r"(b[0]), "r"(b[1]));
}
__device__ __forceinline__ void cpa16(uint32_t dst, const void* src, uint32_t sz) {
    asm volatile("cp.async.cg.shared.global [%0], [%1], 16, %2;"
                 :: "r"(dst), "l"(src), "r"(sz) : "memory");
}
__device__ __forceinline__ void cp_commit() {
    asm volatile("cp.async.commit_group;" ::: "memory");
}
template<int N>
__device__ __forceinline__ void cp_wait() {
    asm volatile("cp.async.wait_group %0;" :: "n"(N) : "memory");
}
// packed fp32x2 fma: acc = v*w + acc  (sm_100-family packed pipe)
__device__ __forceinline__ void fma_x2(unsigned long long& acc, unsigned long long v,
                                       unsigned long long w) {
    asm("fma.rn.f32x2 %0, %1, %2, %0;" : "+l"(acc) : "l"(v), "l"(w));
}
__device__ __forceinline__ unsigned long long pack2(float x, float y) {
    float2 f = make_float2(x, y);
    return *reinterpret_cast<unsigned long long*>(&f);
}
__device__ __forceinline__ float2 unpack2(unsigned long long u) {
    return *reinterpret_cast<float2*>(&u);
}

// ---------------- fused epilogue -------------------------------------------
// EPI: 0 bias->f32 | 3 bias->fp16 | 4 fc1+combine->fp16
//      5 dual fp16: col<DD2 -> xp ; col>=DD2 -> silu -> z
//      6 inline in GEMM (BC pair-product -> atomic s)
template<int EPI>
__device__ __forceinline__ void epi2(int m, int col, int ldc, float v0, float v1,
    const float* __restrict__ bias, float* Cf, __half* Ch, __half* Ch2)
{
    v0 += bias[col]; v1 += bias[col + 1];
    if (EPI == 4) {
        float sv = g_s[m];
        size_t off = (size_t)m * DD2 + col;
        float xc0 = __half2float(g_xco[off]);
        float xc1 = __half2float(g_xco[off + 1]);
        v0 = siluf(xc0 * softplusf(v0) * sv) * __half2float(g_z[off]);
        v1 = siluf(xc1 * softplusf(v1) * sv) * __half2float(g_z[off + 1]);
    }
    if (EPI == 0) {
        *(float2*)(Cf + (size_t)m * ldc + col) = make_float2(v0, v1);
    } else if (EPI == 5) {
        if (col < DD2) {
            *(__half2*)(Ch + (size_t)m * DD2 + col) =
                __halves2half2(__float2half(v0), __float2half(v1));
        } else {
            *(__half2*)(Ch2 + (size_t)m * DD2 + (col - DD2)) =
                __halves2half2(__float2half(siluf(v0)), __float2half(siluf(v1)));
        }
    } else {
        *(__half2*)(Ch + (size_t)m * ldc + col) =
            __halves2half2(__float2half(v0), __float2half(v1));
    }
}

// ---------------- pipelined chunk compute (NKS k-steps, NT<=4 n-tiles) -------
#define STA 0
#define STB 16384
#define STG_SZ 24576
#define SM_TOTAL (2*STG_SZ)

template<int NKS, int NT>
__device__ __forceinline__ void gemm_chunk(uint32_t base, const uint32_t* oa,
                                           const uint32_t* ob, float acc[2][4][4])
{
    if (NT == 0) return;
    constexpr int NP = (NT + 1) / 2;   // B fragments (2 n-tiles each), <=2
    const uint32_t a0 = base + oa[0], a1 = base + oa[1];
#pragma unroll
    for (int ks = 0; ks < NKS; ks++) {
        const uint32_t kx = (uint32_t)(ks * 32);
        uint32_t ah[2][4];
        ldsm4(ah[0], a0 ^ kx);
        ldsm4(ah[1], a1 ^ kx);
        uint32_t rb[4];
        ldsm4(rb, (base + ob[0]) ^ kx);
#pragma unroll
        for (int p = 0; p < NP; p++) {
            uint32_t rnx[4];
            if (p + 1 < NP) ldsm4(rnx, (base + ob[1]) ^ kx);
            uint32_t f0[2] = {rb[0], rb[1]}, f1[2] = {rb[2], rb[3]};
            mma16816(acc[0][2*p],   ah[0], f0);
            mma16816(acc[1][2*p],   ah[1], f0);
            if (2*p + 1 < NT) {
                mma16816(acc[0][2*p+1], ah[0], f1);
                mma16816(acc[1][2*p+1], ah[1], f1);
            }
            if (p + 1 < NP) { rb[0]=rnx[0]; rb[1]=rnx[1]; rb[2]=rnx[2]; rb[3]=rnx[3]; }
        }
    }
}

// ---------------- GEMM: C[M,NWTOT] = epi(A[M,KV] @ B[NWTOT,KV]^T + bias) -----
// CTA tile 128(M) x 64(N), 8 warps = 4M x 2N (warp 32x32), 2-stage cp.async,
// 4 CTAs/SM (192KB smem, 64 regs). NWTOT compile-time for exact N-trim.
template<int EPI, int KV, int NWTOT>
__global__ void __launch_bounds__(256, 4)
mma_gemm(const __half* __restrict__ A, const __half* __restrict__ B,
         const float* __restrict__ bias,
         float* Cf, __half* Ch, __half* Ch2,
         int M, int ldc)
{
    extern __shared__ char smem[];
    const uint32_t sb = sm2u32(smem);
    const int tid  = threadIdx.x;
    const int lane = tid & 31;
    const int wid  = tid >> 5;
    const int wm   = wid & 3;      // 0..3 (M, 32 rows each)
    const int wn   = wid >> 2;     // 0..1 (N, 32 cols each)
    const int m0   = blockIdx.y * 128;
    const int n0   = blockIdx.x * 64;

    constexpr int NFULL = NWTOT / 64;
    constexpr int NREM  = NWTOT % 64;           // multiple of 8
    constexpr int NT0   = NREM ? ((NREM >= 32) ? 4 : NREM / 8) : 4;
    constexpr int NT1   = (NREM > 32) ? (NREM - 32) / 8 : 0;

    const bool full = (NREM == 0) || ((int)blockIdx.x < NFULL);
    const int ntcnt = full ? 4 : (wn ? NT1 : NT0);

    float acc[2][4][4];
#pragma unroll
    for (int i = 0; i < 2; i++)
#pragma unroll
        for (int j = 0; j < 4; j++)
#pragma unroll
            for (int q = 0; q < 4; q++) acc[i][j][q] = 0.f;

    // per-thread swizzled fragment offsets (relative to stage base)
    uint32_t oa[2], ob[2];
    {
#pragma unroll
        for (int mt = 0; mt < 2; mt++) {
            int row = wm * 32 + mt * 16 + (lane & 15);
            oa[mt] = STA + SWZ((uint32_t)(row * 128 + (lane >> 4) * 16));
        }
        const int q    = lane >> 3;
        const int rowo = (q >> 1) * 8 + (lane & 7);
        const int ko   = (q & 1) * 8;
#pragma unroll
        for (int p = 0; p < 2; p++) {
            int row = wn * 32 + p * 16 + rowo;
            ob[p] = STB + SWZ((uint32_t)(row * 128 + ko * 2));
        }
    }

    constexpr int KST  = (KV + 15) >> 4;
    constexpr int KC   = (KST + 3) >> 2;
    constexpr int TAIL = KST - ((KST >> 2) << 2);
    constexpr int TK   = TAIL ? TAIL : 4;

    auto load_stage = [&](int stg, int k0) {
        uint32_t base = sb + stg * STG_SZ;
#pragma unroll
        for (int i = 0; i < 4; i++) {          // A: 128 rows x 64 k
            int idx = tid + i * 256;
            int r = idx >> 3, u = idx & 7;
            int gm = m0 + r, gk = k0 + u * 8;
            bool ok = (gm < M) && (gk < KV);
            size_t go = (size_t)(ok ? gm : 0) * KV + (ok ? gk : 0);
            cpa16(base + STA + SWZ(r * 128 + u * 16), A + go, ok ? 16u : 0u);
        }
#pragma unroll
        for (int i = 0; i < 2; i++) {          // B: 64 rows x 64 k
            int idx = tid + i * 256;
            int r = idx >> 3, u = idx & 7;
            int gn = n0 + r, gk = k0 + u * 8;
            bool ok = (gn < NWTOT) && (gk < KV);
            size_t go = (size_t)(ok ? gn : 0) * KV + (ok ? gk : 0);
            cpa16(base + STB + SWZ(r * 128 + u * 16), B + go, ok ? 16u : 0u);
        }
    };

    load_stage(0, 0);
    cp_commit();

    for (int c = 0; c < KC; c++) {
        if (c + 1 < KC) {
            load_stage((c + 1) & 1, (c + 1) << 6);
            cp_commit();
            cp_wait<1>();
        } else {
            cp_wait<0>();
        }
        __syncthreads();

        const uint32_t base = sb + (c & 1) * STG_SZ;
        const bool lastc = (TAIL != 0) && (c == KC - 1);
        if (full) {
            if (!lastc) gemm_chunk<4, 4>(base, oa, ob, acc);
            else        gemm_chunk<TK, 4>(base, oa, ob, acc);
        } else if (wn == 0) {
            if (!lastc) gemm_chunk<4, NT0>(base, oa, ob, acc);
            else        gemm_chunk<TK, NT0>(base, oa, ob, acc);
        } else {
            if (!lastc) gemm_chunk<4, NT1>(base, oa, ob, acc);
            else        gemm_chunk<TK, NT1>(base, oa, ob, acc);
        }
        __syncthreads();
    }

    // ---- epilogue (column bounds exact by construction) ----
    if (EPI == 6) {
#pragma unroll
        for (int mt = 0; mt < 2; mt++) {
            int r0 = m0 + wm * 32 + mt * 16 + (lane >> 2);
            int r1 = r0 + 8;
            float s0 = 0.f, s1 = 0.f;
#pragma unroll
            for (int nt = 0; nt < 4; nt++) {
                int col = n0 + wn * 32 + nt * 8 + (lane & 3) * 2;
                float b0 = bias[col], b1 = bias[col + 1];
                s0 += (acc[mt][nt][0] + b0) * (acc[mt][nt][1] + b1);
                s1 += (acc[mt][nt][2] + b0) * (acc[mt][nt][3] + b1);
            }
            if (r0 < M) atomicAdd(&g_s[r0], s0);
            if (r1 < M) atomicAdd(&g_s[r1], s1);
        }
    } else {
#pragma unroll
        for (int mt = 0; mt < 2; mt++) {
            int r0 = m0 + wm * 32 + mt * 16 + (lane >> 2);
            int r1 = r0 + 8;
#pragma unroll
            for (int nt = 0; nt < 4; nt++) {
                if (nt < ntcnt) {
                    int col = n0 + wn * 32 + nt * 8 + (lane & 3) * 2;
                    if (r0 < M) epi2<EPI>(r0, col, ldc, acc[mt][nt][0], acc[mt][nt][1], bias, Cf, Ch, Ch2);
                    if (r1 < M) epi2<EPI>(r1, col, ldc, acc[mt][nt][2], acc[mt][nt][3], bias, Cf, Ch, Ch2);
                }
            }
        }
    }
}

// ---------------- weight prep (ONE launch) -----------------------------------
#define SEG_CL  (DD2*DD2)
#define SEG_23  (256*DD2)
#define SEG_F1  (DD2*DD2)
#define SEG_OP  (DM*DD2)
#define SEG_ALL (SEG_CL+SEG_23+SEG_F1+SEG_OP)
#define R0_END  (NL*2*DD2*DM)
#define R1_END  (R0_END + NL*SEG_ALL)
#define R2_END  (R1_END + NL*2*DD2 + NL*256)

__global__ void wprep_all(const float* __restrict__ inw, const float* __restrict__ dww,
                          const float* __restrict__ cl, const float* __restrict__ f2,
                          const float* __restrict__ f3, const float* __restrict__ f1,
                          const float* __restrict__ op,
                          const float* __restrict__ inb, const float* __restrict__ db,
                          const float* __restrict__ f2b, const float* __restrict__ f3b)
{
    int idx = blockIdx.x * blockDim.x + threadIdx.x;
    if (idx < R0_END) {
        const int PER = 2 * DD2 * DM;
        int l = idx / PER, q = idx % PER;
        int n = q / DM, k = q % DM;
        float v = (n < DD2) ? inw[(size_t)l*DM*DD2 + k*DD2 + n]
                            : dww[(size_t)l*DM*DD2 + k*DD2 + (n - DD2)];
        g_wipdw[idx] = __float2half(v);
    } else if (idx < R1_END) {
        int t = idx - R0_END;
        int l = t / SEG_ALL, r = t % SEG_ALL;
        if (r < SEG_CL) {
            int n = r / DD2, k = r % DD2;
            g_wcl[(long)l*SEG_CL + r] = __float2half(cl[(size_t)l*SEG_CL + (size_t)k*DD2 + n]);
        } else if (r < SEG_CL + SEG_23) {
            int q = r - SEG_CL;
            int n = q / DD2, k = q % DD2;
            int j = n >> 1;
            float v = (n & 1) ? f3[(size_t)l*DD2*SSZ + (size_t)k*SSZ + j]
                              : f2[(size_t)l*DD2*SSZ + (size_t)k*SSZ + j];
            g_w23[(long)l*SEG_23 + q] = __float2half(v);
        } else if (r < SEG_CL + SEG_23 + SEG_F1) {
            int q = r - SEG_CL - SEG_23;
            int n = q / DD2, k = q % DD2;
            g_wf1[(long)l*SEG_F1 + q] = __float2half(f1[(size_t)l*SEG_F1 + (size_t)k*DD2 + n]);
        } else {
            int q = r - SEG_CL - SEG_23 - SEG_F1;
            int n = q / DD2, k = q % DD2;
            g_wop[(long)l*SEG_OP + q] = __float2half(op[(size_t)l*SEG_OP + (size_t)k*DM + n]);
        }
    } else if (idx < R2_END) {
        int t = idx - R1_END;
        const int N1 = NL * 2 * DD2;
        if (t < N1) {
            int l = t / (2*DD2), j = t % (2*DD2);
            g_bipdw[t] = (j < DD2) ? inb[l*DD2 + j] : db[l*DD2 + (j - DD2)];
        } else {
            int q = t - N1;
            int l = q / 256, j = q % 256;
            g_b23[q] = (j & 1) ? f3b[l*SSZ + (j >> 1)] : f2b[l*SSZ + (j >> 1)];
        }
    }
}

// ---------------- fused embedding + layer-0 rmsnorm (warp per token) ---------
__global__ void embed_rms_kernel(const float* __restrict__ x, const float* __restrict__ W_in,
                                 const float* __restrict__ b_in, const float* __restrict__ tod,
                                 const float* __restrict__ dow, const float* __restrict__ adp,
                                 const float* __restrict__ nw)
{
    int gwarp = (blockIdx.x * blockDim.x + threadIdx.x) >> 5;
    int lane  = threadIdx.x & 31;
    if (gwarp >= MTOK) return;

    int  t  = gwarp % T_;
    long rn = gwarp / T_;
    int  n  = (int)(rn % NN_);
    int  b  = (int)(rn / NN_);
    const float* xe = x + (((long)(b * T_ + t) * NN_ + n) * 3);
    float e0 = xe[0], e1 = xe[1], e2 = xe[2];
    int ti = (int)(e1 * (float)STEPS); ti = min(max(ti, 0), STEPS - 1);
    int di = (int)e2;                  di = min(max(di, 0), 6);

    float v[5];
    float ss = 0.f;
#pragma unroll
    for (int u = 0; u < 5; u++) {
        int c = lane + u * 32;
        float val = 0.f;
        if (c < DM) {
            if (c < 24)      val = b_in[c] + e0*W_in[c] + e1*W_in[24+c] + e2*W_in[48+c];
            else if (c < 48) val = tod[ti*24 + (c-24)];
            else if (c < 72) val = dow[di*24 + (c-48)];
            else             val = adp[((long)t * NN_ + n) * 80 + (c - 72)];
            ss += val * val;
        }
        v[u] = val;
    }
#pragma unroll
    for (int o = 16; o; o >>= 1) ss += __shfl_xor_sync(0xffffffffu, ss, o);
    float scale = rsqrtf(ss / (float)DM + 1e-5f);

    long base = (long)gwarp * DM;
#pragma unroll
    for (int u = 0; u < 5; u++) {
        int c = lane + u * 32;
        if (c < DM) {
            g_h [base + c] = v[u];
            g_xn[base + c] = __float2half(v[u] * scale * nw[c]);
        }
    }
    if (!lane) g_s[gwarp] = 0.f;
}

// ---------------- rmsnorm (f32 in, fp16 out) ; zeroes g_s --------------------
__global__ void rmsnorm_kernel(const float* __restrict__ w)
{
    int gwarp = (blockIdx.x * blockDim.x + threadIdx.x) >> 5;
    int lane  = threadIdx.x & 31;
    if (gwarp >= MTOK) return;
    const float* row = g_h + (long)gwarp * DM;
    float v[5];
    float ss = 0.f;
#pragma unroll
    for (int u = 0; u < 5; u++) {
        int c = lane + u * 32;
        float val = (c < DM) ? row[c] : 0.f;
        ss += val * val;
        v[u] = val;
    }
#pragma unroll
    for (int o = 16; o; o >>= 1) ss += __shfl_xor_sync(0xffffffffu, ss, o);
    float scale = rsqrtf(ss / (float)DM + 1e-5f);
    long base = (long)gwarp * DM;
#pragma unroll
    for (int u = 0; u < 5; u++) {
        int c = lane + u * 32;
        if (c < DM) g_xn[base + c] = __float2half(v[u] * scale * w[c]);
    }
    if (!lane) g_s[gwarp] = 0.f;
}

// ---------------- conv over T + silu -> fp16 (packed f32x2, pair-per-thread) -
// Each thread owns 2 adjacent d (d0 = 2*pd, d1 = d0+1). Accumulators are
// packed f32x2; per-ti neighbors come from one shfl of the raw half2 word.
#define PCH 5   /* pair-chunks of 32 per row: 5*32=160 >= 152 pairs */
__global__ void conv_silu_kernel(const float* __restrict__ cw, const float* __restrict__ cb)
{
    __shared__ unsigned long long wpk[T_*T_*3];   // packed (w,w)
    __shared__ float bsh[T_];
    for (int i = threadIdx.x; i < T_*T_*3; i += blockDim.x) {
        float w = cw[i];
        wpk[i] = pack2(w, w);
    }
    for (int i = threadIdx.x; i < T_; i += blockDim.x) bsh[i] = cb[i];
    __syncthreads();

    int gw = (int)((blockIdx.x * (long)blockDim.x + threadIdx.x) >> 5);
    if (gw >= ROWS * PCH) return;
    int lane = threadIdx.x & 31;
    int r  = gw / PCH;
    int pc = gw % PCH;
    int pd = pc * 32 + lane;           // pair index
    int d0 = pd * 2;
    bool valid = (d0 < DD2);
    int dcl = valid ? d0 : (DD2 - 2);  // clamp loads for slack threads
    const __half* xrow = g_xp + (long)r * (T_ * DD2);

    uint32_t u[T_];
#pragma unroll
    for (int ti = 0; ti < T_; ti++)
        u[ti] = *(const uint32_t*)(xrow + ti * DD2 + dcl);

    unsigned long long acc[T_];
#pragma unroll
    for (int to = 0; to < T_; to++) acc[to] = pack2(bsh[to], bsh[to]);

#pragma unroll
    for (int ti = 0; ti < T_; ti++) {
        uint32_t up = __shfl_up_sync(0xffffffffu, u[ti], 1);
        uint32_t dn = __shfl_down_sync(0xffffffffu, u[ti], 1);
        float2 cur = __half22float2(*reinterpret_cast<__half2*>(&u[ti]));
        float2 pf  = __half22float2(*reinterpret_cast<__half2*>(&up));
        float2 nf  = __half22float2(*reinterpret_cast<__half2*>(&dn));
        float v0x = pf.y;
        if (lane == 0) v0x = (d0 > 0) ? __half2float(xrow[ti * DD2 + d0 - 1]) : 0.f;
        float v2y = nf.x;
        if (lane == 31) v2y = (d0 + 2 < DD2) ? __half2float(xrow[ti * DD2 + d0 + 2]) : 0.f;
        if (d0 + 2 >= DD2) v2y = 0.f;          // true right edge (incl. mid-warp)
        unsigned long long v0 = pack2(v0x, cur.x);
        unsigned long long v1 = pack2(cur.x, cur.y);
        unsigned long long v2 = pack2(cur.y, v2y);
#pragma unroll
        for (int to = 0; to < T_; to++) {
            const unsigned long long* wp = &wpk[(to * T_ + ti) * 3];
            fma_x2(acc[to], v0, wp[0]);
            fma_x2(acc[to], v1, wp[1]);
            fma_x2(acc[to], v2, wp[2]);
        }
    }
    if (valid) {
        long obase = (long)r * (T_ * DD2) + d0;
#pragma unroll
        for (int to = 0; to < T_; to++) {
            float2 a = unpack2(acc[to]);
            *(__half2*)(g_xca + obase + to * DD2) =
                __halves2half2(__float2half(siluf(a.x)), __float2half(siluf(a.y)));
        }
    }
}

// ---------------- head: smem-cached W_out, 16 rows/block, f32 h --------------
#define OUTR 16
__global__ void out_kernel(const float* __restrict__ Wout, const float* __restrict__ bout,
                           float* __restrict__ out)
{
    extern __shared__ float ws[];   // [12][1824] transposed
    for (int i = threadIdx.x; i < T_*DM*12; i += 384) {
        int k = i / 12, j = i % 12;
        ws[j * (T_*DM) + k] = Wout[i];
    }
    __syncthreads();
    int wj   = threadIdx.x >> 5;    // 0..11
    int lane = threadIdx.x & 31;
    const float* wcol = ws + wj * (T_*DM);
    for (int rr = 0; rr < OUTR; rr++) {
        int rn = blockIdx.x * OUTR + rr;
        if (rn >= ROWS) break;
        const float4* row = (const float4*)(g_h + (long)rn * (T_*DM));
        float acc = 0.f;
        for (int k4 = lane; k4 < (T_*DM)/4; k4 += 32) {
            float4 hv = row[k4];
            acc += hv.x * wcol[4*k4] + hv.y * wcol[4*k4+1]
                 + hv.z * wcol[4*k4+2] + hv.w * wcol[4*k4+3];
        }
#pragma unroll
        for (int o = 16; o; o >>= 1) acc += __shfl_xor_sync(0xffffffffu, acc, o);
        if (!lane) {
            int n = rn % NN_, b = rn / NN_;
            out[((long)b * 12 + wj) * NN_ + n] = acc + bout[wj];
        }
    }
}

// =============================================================================
extern "C" void kernel_launch(void* const* d_in, const int* in_sizes, int n_in,
                              void* d_out, int out_size)
{
    (void)in_sizes; (void)n_in; (void)out_size;
    const float* x        = (const float*)d_in[0];
    const float* W_in     = (const float*)d_in[1];
    const float* b_in     = (const float*)d_in[2];
    const float* tod      = (const float*)d_in[3];
    const float* dow      = (const float*)d_in[4];
    const float* adp      = (const float*)d_in[5];
    const float* norm_w   = (const float*)d_in[6];
    const float* inproj_w = (const float*)d_in[7];
    const float* inproj_b = (const float*)d_in[8];
    const float* conv_w   = (const float*)d_in[9];
    const float* conv_b   = (const float*)d_in[10];
    const float* convlin_w= (const float*)d_in[11];
    const float* convlin_b= (const float*)d_in[12];
    const float* fc1_w    = (const float*)d_in[13];
    const float* fc1_b    = (const float*)d_in[14];
    const float* fc2_w    = (const float*)d_in[15];
    const float* fc2_b    = (const float*)d_in[16];
    const float* fc3_w    = (const float*)d_in[17];
    const float* fc3_b    = (const float*)d_in[18];
    /* d_in[19] = A_ssm unused (h0 == 0) */
    const float* D_w      = (const float*)d_in[20];
    const float* D_b      = (const float*)d_in[21];
    const float* outproj_w= (const float*)d_in[22];
    const float* outproj_b= (const float*)d_in[23];
    const float* W_out    = (const float*)d_in[24];
    const float* b_out    = (const float*)d_in[25];
    float* out = (float*)d_out;

    cudaFuncSetAttribute((const void*)mma_gemm<5,152,608>, cudaFuncAttributeMaxDynamicSharedMemorySize, SM_TOTAL);
    cudaFuncSetAttribute((const void*)mma_gemm<3,304,304>, cudaFuncAttributeMaxDynamicSharedMemorySize, SM_TOTAL);
    cudaFuncSetAttribute((const void*)mma_gemm<6,304,256>, cudaFuncAttributeMaxDynamicSharedMemorySize, SM_TOTAL);
    cudaFuncSetAttribute((const void*)mma_gemm<4,304,304>, cudaFuncAttributeMaxDynamicSharedMemorySize, SM_TOTAL);
    cudaFuncSetAttribute((const void*)mma_gemm<0,304,152>, cudaFuncAttributeMaxDynamicSharedMemorySize, SM_TOTAL);
    cudaFuncSetAttribute((const void*)out_kernel, cudaFuncAttributeMaxDynamicSharedMemorySize,
                         T_*DM*12*(int)sizeof(float));

    void* p;
#define SYM(sym, var, ty) cudaGetSymbolAddress(&p, sym); ty* var = (ty*)p;
    SYM(g_b23,   b23_p,  float)
    SYM(g_bipdw, bipdw_p,float)
    SYM(g_h,     h_p,    float)
    SYM(g_xn,    xn_p,   __half)
    SYM(g_xp,    xp_p,   __half)
    SYM(g_z,     z_p,    __half)
    SYM(g_xca,   xca_p,  __half)
    SYM(g_xco,   xco_p,  __half)
    SYM(g_cb,    cb_p,   __half)
    SYM(g_wipdw, wpd_p,  __half)
    SYM(g_wcl,   wcl_p,  __half)
    SYM(g_w23,   w23_p,  __half)
    SYM(g_wf1,   wf1_p,  __half)
    SYM(g_wop,   wop_p,  __half)
#undef SYM

    // launch 0: fused embedding + layer-0 rmsnorm
    embed_rms_kernel<<<(MTOK*32 + 255)/256, 256>>>(x, W_in, b_in, tod, dow, adp, norm_w);
    // launch 1: all weight prep
    wprep_all<<<(R2_END + 255)/256, 256>>>(inproj_w, D_w, convlin_w, fc2_w, fc3_w,
                                           fc1_w, outproj_w, inproj_b, D_b, fc2_b, fc3_b);

    for (int i = 0; i < NL; i++) {
        if (i > 0)
            rmsnorm_kernel<<<(MTOK*32 + 255)/256, 256>>>(norm_w + i*DM);

        // fused inproj|D_w : xn(152) -> xp(fp16) & z(fp16 silu), N=608
        mma_gemm<5,152,608><<<dim3(10, MTILES), 256, SM_TOTAL>>>(xn_p,
            wpd_p + (long)i*2*DD2*DM, bipdw_p + (long)i*2*DD2,
            nullptr, xp_p, z_p, MTOK, DD2);

        conv_silu_kernel<<<(ROWS*PCH*32 + 255)/256, 256>>>(conv_w + i*T_*T_*3, conv_b + i*T_);

        // convlin: xca(304) -> xco fp16(304)
        mma_gemm<3,304,304><<<dim3(5, MTILES), 256, SM_TOTAL>>>(xca_p,
            wcl_p + (long)i*DD2*DD2, convlin_b + i*DD2,
            nullptr, xco_p, nullptr, MTOK, DD2);

        // fc2|fc3 interleaved: epilogue computes s via pair products + atomics
        mma_gemm<6,304,256><<<dim3(4, MTILES), 256, SM_TOTAL>>>(xco_p,
            w23_p + (long)i*256*DD2, b23_p + i*256,
            nullptr, nullptr, nullptr, MTOK, 256);

        // fc1 + combine fused: -> cb fp16(304)
        mma_gemm<4,304,304><<<dim3(5, MTILES), 256, SM_TOTAL>>>(xco_p,
            wf1_p + (long)i*DD2*DD2, fc1_b + i*DD2,
            nullptr, cb_p, nullptr, MTOK, DD2);

        // outproj: cb(304) -> h f32(152)
        mma_gemm<0,304,152><<<dim3(3, MTILES), 256, SM_TOTAL>>>(cb_p,
            wop_p + (long)i*DM*DD2, outproj_b + i*DM,
            h_p, nullptr, nullptr, MTOK, DM);
    }

    out_kernel<<<(ROWS + OUTR - 1)/OUTR, 384, T_*DM*12*sizeof(float)>>>(W_out, b_out, out);
}